// round 1
// baseline (speedup 1.0000x reference)
#include <cuda_runtime.h>
#include <math.h>

// Problem constants
#define BB   2
#define SS   2048
#define DD   1024
#define HH   16
#define HDIM 64
#define TOK  (BB*SS)          // 4096 rows
#define NSCALE 0.125f          // 1/sqrt(64)

// ---------------------------------------------------------------------------
// Scratch (static __device__ arrays; no allocation allowed)
// ---------------------------------------------------------------------------
__device__ float g_xq[TOK*DD];
__device__ float g_xk[TOK*DD];
__device__ float g_xv[TOK*DD];
__device__ float g_Q [TOK*DD];   // head layout [B,H,S,HD]
__device__ float g_K [TOK*DD];
__device__ float g_V [TOK*DD];
__device__ float g_Q2[TOK*DD];   // after Hopfield update step
__device__ float g_O [TOK*DD];   // attention output, head layout

// ---------------------------------------------------------------------------
// Block reduction (256 threads)
// ---------------------------------------------------------------------------
__device__ __forceinline__ float blk_sum256(float v) {
    __shared__ float red[8];
    int lane = threadIdx.x & 31;
    int w    = threadIdx.x >> 5;
    #pragma unroll
    for (int o = 16; o > 0; o >>= 1) v += __shfl_xor_sync(0xffffffffu, v, o);
    __syncthreads();              // protect red[] from previous call
    if (lane == 0) red[w] = v;
    __syncthreads();
    float tot = red[0] + red[1] + red[2] + red[3] + red[4] + red[5] + red[6] + red[7];
    return tot;
}

// ---------------------------------------------------------------------------
// Fused triple LayerNorm: one normalization, three affine outputs
// grid = TOK blocks, 256 threads; each thread handles 4 contiguous columns
// ---------------------------------------------------------------------------
__global__ __launch_bounds__(256) void ln3_kernel(
    const float* __restrict__ data,
    const float* __restrict__ gk, const float* __restrict__ bk,
    const float* __restrict__ gq, const float* __restrict__ bq,
    const float* __restrict__ gv, const float* __restrict__ bv,
    float* __restrict__ xq, float* __restrict__ xk, float* __restrict__ xv)
{
    int row = blockIdx.x;
    int t   = threadIdx.x;
    const float4 x4 = ((const float4*)(data + (size_t)row * DD))[t];
    float s = x4.x + x4.y + x4.z + x4.w;
    float mean = blk_sum256(s) * (1.0f / DD);
    float d0 = x4.x - mean, d1 = x4.y - mean, d2 = x4.z - mean, d3 = x4.w - mean;
    float sq = d0*d0 + d1*d1 + d2*d2 + d3*d3;
    float var = blk_sum256(sq) * (1.0f / DD);
    float r = rsqrtf(var + 1e-5f);
    float n0 = d0*r, n1 = d1*r, n2 = d2*r, n3 = d3*r;

    float4 g4, b4, o4;
    size_t base = (size_t)row * DD;

    g4 = ((const float4*)gq)[t]; b4 = ((const float4*)bq)[t];
    o4.x = n0*g4.x + b4.x; o4.y = n1*g4.y + b4.y; o4.z = n2*g4.z + b4.z; o4.w = n3*g4.w + b4.w;
    ((float4*)(xq + base))[t] = o4;

    g4 = ((const float4*)gk)[t]; b4 = ((const float4*)bk)[t];
    o4.x = n0*g4.x + b4.x; o4.y = n1*g4.y + b4.y; o4.z = n2*g4.z + b4.z; o4.w = n3*g4.w + b4.w;
    ((float4*)(xk + base))[t] = o4;

    g4 = ((const float4*)gv)[t]; b4 = ((const float4*)bv)[t];
    o4.x = n0*g4.x + b4.x; o4.y = n1*g4.y + b4.y; o4.z = n2*g4.z + b4.z; o4.w = n3*g4.w + b4.w;
    ((float4*)(xv + base))[t] = o4;
}

// ---------------------------------------------------------------------------
// SGEMM: C[M=4096, N=1024] = A[4096x1024] * W[1024x1024] + bias
// BM=BN=128, BK=8, 256 threads, 8x8 per-thread microtile (split 2x2 of 4x4)
// MODE_IN : 0 = A row-major [M,K];  1 = A in head layout [B,H,S,HD] (gather)
// MODE_OUT: 0 = C row-major [M,N];  1 = C in head layout (scatter)
// ---------------------------------------------------------------------------
template<int MODE_IN, int MODE_OUT>
__global__ __launch_bounds__(256) void gemm_kernel(
    const float* __restrict__ A, const float* __restrict__ W,
    const float* __restrict__ bias, float* __restrict__ C)
{
    constexpr int BM = 128, BN = 128, BK = 8;
    constexpr int N = DD, K = DD;
    __shared__ float As[BK][BM];
    __shared__ float Bs[BK][BN];

    int tid = threadIdx.x;
    int bm = blockIdx.y * BM;
    int bn = blockIdx.x * BN;
    int tx = tid & 15;
    int ty = tid >> 4;

    // A tile load mapping: 128 rows x 8 k, one float4 per thread
    int arow  = tid >> 1;           // 0..127
    int acol4 = (tid & 1) * 4;      // 0 or 4
    // B tile load mapping: 8 rows x 128 cols
    int bkrow = tid >> 5;           // 0..7
    int bcol4 = (tid & 31) * 4;     // 0..124

    float acc[8][8];
    #pragma unroll
    for (int i = 0; i < 8; i++)
        #pragma unroll
        for (int j = 0; j < 8; j++) acc[i][j] = 0.f;

    for (int kk = 0; kk < K; kk += BK) {
        // ---- load A tile ----
        int gm = bm + arow;
        int gk = kk + acol4;
        float4 av;
        if (MODE_IN == 0) {
            av = *(const float4*)&A[(size_t)gm * K + gk];
        } else {
            int b  = gm >> 11, s2 = gm & (SS - 1);
            int h  = gk >> 6,  hd = gk & (HDIM - 1);
            av = *(const float4*)&A[(((size_t)(b*HH + h) * SS + s2) * HDIM) + hd];
        }
        As[acol4 + 0][arow] = av.x;
        As[acol4 + 1][arow] = av.y;
        As[acol4 + 2][arow] = av.z;
        As[acol4 + 3][arow] = av.w;
        // ---- load B tile ----
        *(float4*)&Bs[bkrow][bcol4] =
            *(const float4*)&W[(size_t)(kk + bkrow) * N + bn + bcol4];
        __syncthreads();

        #pragma unroll
        for (int k = 0; k < BK; k++) {
            float a0[4], a1[4], b0[4], b1[4];
            *(float4*)a0 = *(const float4*)&As[k][ty * 4];
            *(float4*)a1 = *(const float4*)&As[k][64 + ty * 4];
            *(float4*)b0 = *(const float4*)&Bs[k][tx * 4];
            *(float4*)b1 = *(const float4*)&Bs[k][64 + tx * 4];
            #pragma unroll
            for (int i = 0; i < 4; i++)
                #pragma unroll
                for (int j = 0; j < 4; j++) {
                    acc[i  ][j  ] += a0[i] * b0[j];
                    acc[i  ][j+4] += a0[i] * b1[j];
                    acc[i+4][j  ] += a1[i] * b0[j];
                    acc[i+4][j+4] += a1[i] * b1[j];
                }
        }
        __syncthreads();
    }

    // ---- epilogue ----
    int cb0 = bn + tx * 4;
    int cb1 = bn + 64 + tx * 4;
    float4 bias0 = *(const float4*)&bias[cb0];
    float4 bias1 = *(const float4*)&bias[cb1];

    #pragma unroll
    for (int i = 0; i < 8; i++) {
        int gr = bm + ((i < 4) ? (ty * 4 + i) : (64 + ty * 4 + (i - 4)));
        float4 v0 = make_float4(acc[i][0] + bias0.x, acc[i][1] + bias0.y,
                                acc[i][2] + bias0.z, acc[i][3] + bias0.w);
        float4 v1 = make_float4(acc[i][4] + bias1.x, acc[i][5] + bias1.y,
                                acc[i][6] + bias1.z, acc[i][7] + bias1.w);
        if (MODE_OUT == 0) {
            *(float4*)&C[(size_t)gr * N + cb0] = v0;
            *(float4*)&C[(size_t)gr * N + cb1] = v1;
        } else {
            int b = gr >> 11, s2 = gr & (SS - 1);
            int h0 = cb0 >> 6, hd0 = cb0 & (HDIM - 1);
            int h1 = cb1 >> 6, hd1 = cb1 & (HDIM - 1);
            *(float4*)&C[((size_t)(b*HH + h0) * SS + s2) * HDIM + hd0] = v0;
            *(float4*)&C[((size_t)(b*HH + h1) * SS + s2) * HDIM + hd1] = v1;
        }
    }
}

// ---------------------------------------------------------------------------
// Flash attention pass: Out = softmax(scale * Qin Kin^T) @ Vin
// grid = (S/128, B*H); 128 threads, one query row per thread.
// HD=64: q and acc live fully in registers; K/V tiles (64 keys) in smem.
// ---------------------------------------------------------------------------
__global__ __launch_bounds__(128) void attn_kernel(
    const float* __restrict__ Qin, const float* __restrict__ Kin,
    const float* __restrict__ Vin, float* __restrict__ Out)
{
    __shared__ float Ks[64][HDIM];
    __shared__ float Vs[64][HDIM];

    int bh = blockIdx.y;
    int q  = blockIdx.x * 128 + threadIdx.x;
    size_t bhbase = (size_t)bh * SS * HDIM;

    float qr[HDIM];
    {
        const float4* qp = (const float4*)(Qin + bhbase + (size_t)q * HDIM);
        #pragma unroll
        for (int i = 0; i < 16; i++) {
            float4 v = qp[i];
            qr[4*i] = v.x; qr[4*i+1] = v.y; qr[4*i+2] = v.z; qr[4*i+3] = v.w;
        }
    }

    float acc[HDIM];
    #pragma unroll
    for (int i = 0; i < HDIM; i++) acc[i] = 0.f;
    float m = -1e30f, l = 0.f;

    int r    = threadIdx.x >> 1;        // 0..63 (tile row to load)
    int half = (threadIdx.x & 1) * 32;  // 0 or 32

    for (int kt = 0; kt < SS / 64; kt++) {
        // cooperative load of K and V tiles (64 x 64 each)
        {
            const float4* ksrc = (const float4*)(Kin + bhbase + (size_t)(kt*64 + r) * HDIM + half);
            const float4* vsrc = (const float4*)(Vin + bhbase + (size_t)(kt*64 + r) * HDIM + half);
            float4* kd = (float4*)&Ks[r][half];
            float4* vd = (float4*)&Vs[r][half];
            #pragma unroll
            for (int i = 0; i < 8; i++) kd[i] = ksrc[i];
            #pragma unroll
            for (int i = 0; i < 8; i++) vd[i] = vsrc[i];
        }
        __syncthreads();

        #pragma unroll
        for (int cc = 0; cc < 4; cc++) {       // 4 chunks of 16 keys
            float s[16];
            float cm = -1e30f;
            #pragma unroll
            for (int j = 0; j < 16; j++) {
                const float4* kr = (const float4*)&Ks[cc*16 + j][0];
                float d = 0.f;
                #pragma unroll
                for (int i = 0; i < 16; i++) {
                    float4 kv = kr[i];
                    d += qr[4*i]*kv.x + qr[4*i+1]*kv.y + qr[4*i+2]*kv.z + qr[4*i+3]*kv.w;
                }
                s[j] = d * NSCALE;
                cm = fmaxf(cm, s[j]);
            }
            float mn   = fmaxf(m, cm);
            float corr = __expf(m - mn);
            m = mn;
            l *= corr;
            #pragma unroll
            for (int i = 0; i < HDIM; i++) acc[i] *= corr;
            #pragma unroll
            for (int j = 0; j < 16; j++) {
                float p = __expf(s[j] - m);
                l += p;
                const float4* vr = (const float4*)&Vs[cc*16 + j][0];
                #pragma unroll
                for (int i = 0; i < 16; i++) {
                    float4 vv = vr[i];
                    acc[4*i]   += p * vv.x;
                    acc[4*i+1] += p * vv.y;
                    acc[4*i+2] += p * vv.z;
                    acc[4*i+3] += p * vv.w;
                }
            }
        }
        __syncthreads();
    }

    float inv = 1.f / l;
    float4* op = (float4*)(Out + bhbase + (size_t)q * HDIM);
    #pragma unroll
    for (int i = 0; i < 16; i++) {
        float4 v = make_float4(acc[4*i]*inv, acc[4*i+1]*inv, acc[4*i+2]*inv, acc[4*i+3]*inv);
        op[i] = v;
    }
}

// ---------------------------------------------------------------------------
// Launch
// ---------------------------------------------------------------------------
extern "C" void kernel_launch(void* const* d_in, const int* in_sizes, int n_in,
                              void* d_out, int out_size)
{
    const float* data = (const float*)d_in[0];
    const float* gk   = (const float*)d_in[1];
    const float* bk   = (const float*)d_in[2];
    const float* gq   = (const float*)d_in[3];
    const float* bq   = (const float*)d_in[4];
    const float* gv   = (const float*)d_in[5];
    const float* bv   = (const float*)d_in[6];
    const float* Wq   = (const float*)d_in[7];
    const float* bq2  = (const float*)d_in[8];
    const float* Wk   = (const float*)d_in[9];
    const float* bk2  = (const float*)d_in[10];
    const float* Wv   = (const float*)d_in[11];
    const float* bv2  = (const float*)d_in[12];
    const float* Wo   = (const float*)d_in[13];
    const float* bo   = (const float*)d_in[14];
    float* out = (float*)d_out;

    float *xq, *xk, *xv, *Q, *K, *V, *Q2, *O;
    cudaGetSymbolAddress((void**)&xq, g_xq);
    cudaGetSymbolAddress((void**)&xk, g_xk);
    cudaGetSymbolAddress((void**)&xv, g_xv);
    cudaGetSymbolAddress((void**)&Q,  g_Q);
    cudaGetSymbolAddress((void**)&K,  g_K);
    cudaGetSymbolAddress((void**)&V,  g_V);
    cudaGetSymbolAddress((void**)&Q2, g_Q2);
    cudaGetSymbolAddress((void**)&O,  g_O);

    ln3_kernel<<<TOK, 256>>>(data, gk, bk, gq, bq, gv, bv, xq, xk, xv);

    dim3 ggrid(DD / 128, TOK / 128);           // (8, 32)
    gemm_kernel<0,1><<<ggrid, 256>>>(xq, Wq, bq2, Q);
    gemm_kernel<0,1><<<ggrid, 256>>>(xk, Wk, bk2, K);
    gemm_kernel<0,1><<<ggrid, 256>>>(xv, Wv, bv2, V);

    dim3 agrid(SS / 128, BB * HH);             // (16, 32)
    attn_kernel<<<agrid, 128>>>(Q,  K, K, Q2); // Hopfield update: q <- softmax(bQK^T) K
    attn_kernel<<<agrid, 128>>>(Q2, K, V, O);  // retrieval with values

    gemm_kernel<1,0><<<ggrid, 256>>>(O, Wo, bo, out);
}

// round 2
// speedup vs baseline: 4.1231x; 4.1231x over previous
#include <cuda_runtime.h>
#include <math.h>

// Problem constants
#define BB   2
#define SS   2048
#define DD   1024
#define HH   16
#define HDIM 64
#define TOK  (BB*SS)           // 4096 rows
#define NSCALE 0.125f          // 1/sqrt(64)

// ---------------------------------------------------------------------------
// Scratch (static __device__ arrays; no allocation allowed)
// ---------------------------------------------------------------------------
__device__ float g_xq[TOK*DD];
__device__ float g_xk[TOK*DD];
__device__ float g_xv[TOK*DD];
__device__ float g_Q [TOK*DD];   // head layout [B,H,S,HD]
__device__ float g_K [TOK*DD];
__device__ float g_V [TOK*DD];
__device__ float g_Q2[TOK*DD];
__device__ float g_O [TOK*DD];

// ---------------------------------------------------------------------------
// tf32 helpers
// ---------------------------------------------------------------------------
__device__ __forceinline__ float tf32r(float x) {
    unsigned u;
    asm("cvt.rna.tf32.f32 %0, %1;" : "=r"(u) : "f"(x));
    return __uint_as_float(u);
}

__device__ __forceinline__ void mma8(float* d, const unsigned* a, unsigned b0, unsigned b1) {
    asm volatile(
        "mma.sync.aligned.m16n8k8.row.col.f32.tf32.tf32.f32 "
        "{%0,%1,%2,%3}, {%4,%5,%6,%7}, {%8,%9}, {%0,%1,%2,%3};"
        : "+f"(d[0]), "+f"(d[1]), "+f"(d[2]), "+f"(d[3])
        : "r"(a[0]), "r"(a[1]), "r"(a[2]), "r"(a[3]), "r"(b0), "r"(b1));
}

// ---------------------------------------------------------------------------
// Block reduction (256 threads)
// ---------------------------------------------------------------------------
__device__ __forceinline__ float blk_sum256(float v) {
    __shared__ float red[8];
    int lane = threadIdx.x & 31;
    int w    = threadIdx.x >> 5;
    #pragma unroll
    for (int o = 16; o > 0; o >>= 1) v += __shfl_xor_sync(0xffffffffu, v, o);
    __syncthreads();
    if (lane == 0) red[w] = v;
    __syncthreads();
    return red[0]+red[1]+red[2]+red[3]+red[4]+red[5]+red[6]+red[7];
}

// ---------------------------------------------------------------------------
// Fused triple LayerNorm
// ---------------------------------------------------------------------------
__global__ __launch_bounds__(256) void ln3_kernel(
    const float* __restrict__ data,
    const float* __restrict__ gk, const float* __restrict__ bk,
    const float* __restrict__ gq, const float* __restrict__ bq,
    const float* __restrict__ gv, const float* __restrict__ bv,
    float* __restrict__ xq, float* __restrict__ xk, float* __restrict__ xv)
{
    int row = blockIdx.x;
    int t   = threadIdx.x;
    const float4 x4 = ((const float4*)(data + (size_t)row * DD))[t];
    float s = x4.x + x4.y + x4.z + x4.w;
    float mean = blk_sum256(s) * (1.0f / DD);
    float d0 = x4.x - mean, d1 = x4.y - mean, d2 = x4.z - mean, d3 = x4.w - mean;
    float sq = d0*d0 + d1*d1 + d2*d2 + d3*d3;
    float var = blk_sum256(sq) * (1.0f / DD);
    float r = rsqrtf(var + 1e-5f);
    float n0 = d0*r, n1 = d1*r, n2 = d2*r, n3 = d3*r;

    float4 g4, b4, o4;
    size_t base = (size_t)row * DD;

    g4 = ((const float4*)gq)[t]; b4 = ((const float4*)bq)[t];
    o4.x = n0*g4.x + b4.x; o4.y = n1*g4.y + b4.y; o4.z = n2*g4.z + b4.z; o4.w = n3*g4.w + b4.w;
    ((float4*)(xq + base))[t] = o4;

    g4 = ((const float4*)gk)[t]; b4 = ((const float4*)bk)[t];
    o4.x = n0*g4.x + b4.x; o4.y = n1*g4.y + b4.y; o4.z = n2*g4.z + b4.z; o4.w = n3*g4.w + b4.w;
    ((float4*)(xk + base))[t] = o4;

    g4 = ((const float4*)gv)[t]; b4 = ((const float4*)bv)[t];
    o4.x = n0*g4.x + b4.x; o4.y = n1*g4.y + b4.y; o4.z = n2*g4.z + b4.z; o4.w = n3*g4.w + b4.w;
    ((float4*)(xv + base))[t] = o4;
}

// ---------------------------------------------------------------------------
// tf32 tensor-core GEMM: C[4096,1024] = A[4096,1024] @ W[1024,1024] + bias
// BM=128 BN=128 BK=16, 256 thr = 8 warps (2x4), warp tile 64x32.
// MODE_IN : 0 = A row-major;  1 = A head-layout gather
// MODE_OUT: 0 = C row-major;  1 = C head-layout scatter
// ---------------------------------------------------------------------------
template<int MODE_IN, int MODE_OUT>
__global__ __launch_bounds__(256) void gemm_mma(
    const float* __restrict__ A, const float* __restrict__ W,
    const float* __restrict__ bias, float* __restrict__ C)
{
    constexpr int BM = 128, BN = 128, BK = 16;
    constexpr int APAD = 20;    // row pitch for As (floats)
    constexpr int BPAD = 136;   // row pitch for Bs (floats)
    __shared__ float As[BM * APAD];
    __shared__ float Bs[BK * BPAD];

    int tid  = threadIdx.x;
    int lane = tid & 31;
    int w    = tid >> 5;
    int g    = lane >> 2;       // groupID 0..7
    int t    = lane & 3;        // thread-in-group 0..3
    int wm   = (w >> 2) * 64;   // warp M offset
    int wn   = (w & 3) * 32;    // warp N offset
    int bm   = blockIdx.y * BM;
    int bn   = blockIdx.x * BN;

    // global->smem mapping
    int ar = tid >> 1;          // 0..127
    int ac = (tid & 1) * 8;     // 0 or 8
    int br = tid >> 4;          // 0..15
    int bc = (tid & 15) * 8;    // 0..120

    float acc[4][4][4];
    #pragma unroll
    for (int i = 0; i < 4; i++)
        #pragma unroll
        for (int j = 0; j < 4; j++)
            #pragma unroll
            for (int q = 0; q < 4; q++) acc[i][j][q] = 0.f;

    for (int kk = 0; kk < DD; kk += BK) {
        // ---- load A tile (tf32-round on store) ----
        float4 a0, a1;
        int gm = bm + ar;
        int gk = kk + ac;
        if (MODE_IN == 0) {
            const float* p = &A[(size_t)gm * DD + gk];
            a0 = *(const float4*)p;
            a1 = *(const float4*)(p + 4);
        } else {
            int b  = gm >> 11, s2 = gm & (SS - 1);
            int h  = gk >> 6,  hd = gk & (HDIM - 1);
            const float* p = &A[(((size_t)(b*HH + h) * SS + s2) * HDIM) + hd];
            a0 = *(const float4*)p;
            a1 = *(const float4*)(p + 4);
        }
        {
            float* d = &As[ar * APAD + ac];
            *(float4*)d       = make_float4(tf32r(a0.x), tf32r(a0.y), tf32r(a0.z), tf32r(a0.w));
            *(float4*)(d + 4) = make_float4(tf32r(a1.x), tf32r(a1.y), tf32r(a1.z), tf32r(a1.w));
        }
        // ---- load B tile ----
        {
            const float* p = &W[(size_t)(kk + br) * DD + bn + bc];
            float4 b0 = *(const float4*)p;
            float4 b1 = *(const float4*)(p + 4);
            float* d = &Bs[br * BPAD + bc];
            *(float4*)d       = make_float4(tf32r(b0.x), tf32r(b0.y), tf32r(b0.z), tf32r(b0.w));
            *(float4*)(d + 4) = make_float4(tf32r(b1.x), tf32r(b1.y), tf32r(b1.z), tf32r(b1.w));
        }
        __syncthreads();

        #pragma unroll
        for (int ks = 0; ks < 2; ks++) {
            int k0 = ks * 8;
            unsigned af[4][4], bf[4][2];
            #pragma unroll
            for (int mi = 0; mi < 4; mi++) {
                int r = wm + mi * 16 + g;
                af[mi][0] = __float_as_uint(As[(r    ) * APAD + k0 + t    ]);
                af[mi][1] = __float_as_uint(As[(r + 8) * APAD + k0 + t    ]);
                af[mi][2] = __float_as_uint(As[(r    ) * APAD + k0 + t + 4]);
                af[mi][3] = __float_as_uint(As[(r + 8) * APAD + k0 + t + 4]);
            }
            #pragma unroll
            for (int ni = 0; ni < 4; ni++) {
                int c = wn + ni * 8 + g;
                bf[ni][0] = __float_as_uint(Bs[(k0 + t    ) * BPAD + c]);
                bf[ni][1] = __float_as_uint(Bs[(k0 + t + 4) * BPAD + c]);
            }
            #pragma unroll
            for (int mi = 0; mi < 4; mi++)
                #pragma unroll
                for (int ni = 0; ni < 4; ni++)
                    mma8(acc[mi][ni], af[mi], bf[ni][0], bf[ni][1]);
        }
        __syncthreads();
    }

    // ---- epilogue ----
    #pragma unroll
    for (int mi = 0; mi < 4; mi++) {
        #pragma unroll
        for (int ni = 0; ni < 4; ni++) {
            int row = bm + wm + mi * 16 + g;
            int col = bn + wn + ni * 8 + 2 * t;
            float2 bia = *(const float2*)&bias[col];
            float2 v0 = make_float2(acc[mi][ni][0] + bia.x, acc[mi][ni][1] + bia.y);
            float2 v1 = make_float2(acc[mi][ni][2] + bia.x, acc[mi][ni][3] + bia.y);
            if (MODE_OUT == 0) {
                *(float2*)&C[(size_t)row * DD + col]       = v0;
                *(float2*)&C[(size_t)(row + 8) * DD + col] = v1;
            } else {
                int h = col >> 6, hd = col & (HDIM - 1);
                int b0i = row >> 11,      s0 = row & (SS - 1);
                int b1i = (row + 8) >> 11, s1 = (row + 8) & (SS - 1);
                *(float2*)&C[((size_t)(b0i*HH + h) * SS + s0) * HDIM + hd] = v0;
                *(float2*)&C[((size_t)(b1i*HH + h) * SS + s1) * HDIM + hd] = v1;
            }
        }
    }
}

// ---------------------------------------------------------------------------
// Flash attention with tf32 mma: Out = softmax(NSCALE * Qin Kin^T) @ Vin
// grid = (S/64, B*H); 128 threads = 4 warps; warp owns 16 query rows.
// Dynamic smem: Ks[64][68] | Vs[64][72] | Ps[4][16][68]
// ---------------------------------------------------------------------------
#define KSP 68
#define VSP 72
#define PSP 68
#define ATTN_SMEM ((64*KSP + 64*VSP + 4*16*PSP) * 4)

__global__ __launch_bounds__(128) void attn_mma(
    const float* __restrict__ Qin, const float* __restrict__ Kin,
    const float* __restrict__ Vin, float* __restrict__ Out)
{
    extern __shared__ float sm[];
    float* Ks = sm;                       // [64][KSP]
    float* Vs = sm + 64 * KSP;            // [64][VSP]
    float* Ps = sm + 64 * KSP + 64 * VSP; // [4][16][PSP]

    int lane = threadIdx.x & 31;
    int w    = threadIdx.x >> 5;
    int g    = lane >> 2;
    int t    = lane & 3;
    int bh   = blockIdx.y;
    int q0   = blockIdx.x * 64;
    size_t base = (size_t)bh * SS * HDIM;

    // Q fragments, pre-scaled by beta, resident for the whole kernel
    unsigned qa[8][4];
    {
        const float* Qp = Qin + base;
        int r0 = q0 + w * 16 + g;
        #pragma unroll
        for (int ks = 0; ks < 8; ks++) {
            qa[ks][0] = __float_as_uint(tf32r(Qp[(size_t)r0      * HDIM + ks*8 + t    ] * NSCALE));
            qa[ks][1] = __float_as_uint(tf32r(Qp[(size_t)(r0+8)  * HDIM + ks*8 + t    ] * NSCALE));
            qa[ks][2] = __float_as_uint(tf32r(Qp[(size_t)r0      * HDIM + ks*8 + t + 4] * NSCALE));
            qa[ks][3] = __float_as_uint(tf32r(Qp[(size_t)(r0+8)  * HDIM + ks*8 + t + 4] * NSCALE));
        }
    }

    float o[8][4];
    #pragma unroll
    for (int j = 0; j < 8; j++)
        #pragma unroll
        for (int q = 0; q < 4; q++) o[j][q] = 0.f;
    float m0 = -1e30f, m1 = -1e30f, l0 = 0.f, l1 = 0.f;

    int lrow = threadIdx.x >> 1;          // 0..63
    int lcol = (threadIdx.x & 1) * 32;    // 0 or 32

    for (int kt = 0; kt < SS / 64; kt++) {
        // ---- cooperative K/V tile load (tf32 round on store) ----
        {
            const float* Kp = Kin + base + (size_t)(kt*64 + lrow) * HDIM + lcol;
            const float* Vp = Vin + base + (size_t)(kt*64 + lrow) * HDIM + lcol;
            float* kd = &Ks[lrow * KSP + lcol];
            float* vd = &Vs[lrow * VSP + lcol];
            #pragma unroll
            for (int i = 0; i < 8; i++) {
                float4 v = *(const float4*)(Kp + i*4);
                *(float4*)(kd + i*4) = make_float4(tf32r(v.x), tf32r(v.y), tf32r(v.z), tf32r(v.w));
            }
            #pragma unroll
            for (int i = 0; i < 8; i++) {
                float4 v = *(const float4*)(Vp + i*4);
                *(float4*)(vd + i*4) = make_float4(tf32r(v.x), tf32r(v.y), tf32r(v.z), tf32r(v.w));
            }
        }
        __syncthreads();

        // ---- S = Q K^T  (per warp 16x64) ----
        float s[8][4];
        #pragma unroll
        for (int n = 0; n < 8; n++)
            #pragma unroll
            for (int q = 0; q < 4; q++) s[n][q] = 0.f;

        #pragma unroll
        for (int ks = 0; ks < 8; ks++) {
            #pragma unroll
            for (int n = 0; n < 8; n++) {
                unsigned b0 = __float_as_uint(Ks[(n*8 + g) * KSP + ks*8 + t    ]);
                unsigned b1 = __float_as_uint(Ks[(n*8 + g) * KSP + ks*8 + t + 4]);
                mma8(s[n], qa[ks], b0, b1);
            }
        }

        // ---- online softmax ----
        float tm0 = -1e30f, tm1 = -1e30f;
        #pragma unroll
        for (int n = 0; n < 8; n++) {
            tm0 = fmaxf(tm0, fmaxf(s[n][0], s[n][1]));
            tm1 = fmaxf(tm1, fmaxf(s[n][2], s[n][3]));
        }
        tm0 = fmaxf(tm0, __shfl_xor_sync(0xffffffffu, tm0, 1));
        tm0 = fmaxf(tm0, __shfl_xor_sync(0xffffffffu, tm0, 2));
        tm1 = fmaxf(tm1, __shfl_xor_sync(0xffffffffu, tm1, 1));
        tm1 = fmaxf(tm1, __shfl_xor_sync(0xffffffffu, tm1, 2));

        float nm0 = fmaxf(m0, tm0), nm1 = fmaxf(m1, tm1);
        float c0 = __expf(m0 - nm0), c1 = __expf(m1 - nm1);
        m0 = nm0; m1 = nm1;

        float ps0 = 0.f, ps1 = 0.f;
        float* Pw = Ps + w * 16 * PSP;
        #pragma unroll
        for (int n = 0; n < 8; n++) {
            float p0 = __expf(s[n][0] - m0);
            float p1 = __expf(s[n][1] - m0);
            float p2 = __expf(s[n][2] - m1);
            float p3 = __expf(s[n][3] - m1);
            ps0 += p0 + p1;
            ps1 += p2 + p3;
            Pw[ g      * PSP + n*8 + 2*t    ] = tf32r(p0);
            Pw[ g      * PSP + n*8 + 2*t + 1] = tf32r(p1);
            Pw[(g + 8) * PSP + n*8 + 2*t    ] = tf32r(p2);
            Pw[(g + 8) * PSP + n*8 + 2*t + 1] = tf32r(p3);
        }
        ps0 += __shfl_xor_sync(0xffffffffu, ps0, 1);
        ps0 += __shfl_xor_sync(0xffffffffu, ps0, 2);
        ps1 += __shfl_xor_sync(0xffffffffu, ps1, 1);
        ps1 += __shfl_xor_sync(0xffffffffu, ps1, 2);
        l0 = l0 * c0 + ps0;
        l1 = l1 * c1 + ps1;
        #pragma unroll
        for (int j = 0; j < 8; j++) {
            o[j][0] *= c0; o[j][1] *= c0;
            o[j][2] *= c1; o[j][3] *= c1;
        }
        __syncwarp();

        // ---- O += P V  (per warp 16x64) ----
        #pragma unroll
        for (int ks = 0; ks < 8; ks++) {
            unsigned pa[4];
            pa[0] = __float_as_uint(Pw[ g      * PSP + ks*8 + t    ]);
            pa[1] = __float_as_uint(Pw[(g + 8) * PSP + ks*8 + t    ]);
            pa[2] = __float_as_uint(Pw[ g      * PSP + ks*8 + t + 4]);
            pa[3] = __float_as_uint(Pw[(g + 8) * PSP + ks*8 + t + 4]);
            #pragma unroll
            for (int j = 0; j < 8; j++) {
                unsigned b0 = __float_as_uint(Vs[(ks*8 + t    ) * VSP + j*8 + g]);
                unsigned b1 = __float_as_uint(Vs[(ks*8 + t + 4) * VSP + j*8 + g]);
                mma8(o[j], pa, b0, b1);
            }
        }
        __syncthreads();
    }

    // ---- epilogue ----
    float inv0 = 1.f / l0, inv1 = 1.f / l1;
    int r0 = q0 + w * 16 + g;
    float* Op = Out + base;
    #pragma unroll
    for (int j = 0; j < 8; j++) {
        *(float2*)&Op[(size_t)r0      * HDIM + j*8 + 2*t] =
            make_float2(o[j][0] * inv0, o[j][1] * inv0);
        *(float2*)&Op[(size_t)(r0+8)  * HDIM + j*8 + 2*t] =
            make_float2(o[j][2] * inv1, o[j][3] * inv1);
    }
}

// ---------------------------------------------------------------------------
// Launch
// ---------------------------------------------------------------------------
extern "C" void kernel_launch(void* const* d_in, const int* in_sizes, int n_in,
                              void* d_out, int out_size)
{
    const float* data = (const float*)d_in[0];
    const float* gk   = (const float*)d_in[1];
    const float* bk   = (const float*)d_in[2];
    const float* gq   = (const float*)d_in[3];
    const float* bq   = (const float*)d_in[4];
    const float* gv   = (const float*)d_in[5];
    const float* bv   = (const float*)d_in[6];
    const float* Wq   = (const float*)d_in[7];
    const float* bq2  = (const float*)d_in[8];
    const float* Wk   = (const float*)d_in[9];
    const float* bk2  = (const float*)d_in[10];
    const float* Wv   = (const float*)d_in[11];
    const float* bv2  = (const float*)d_in[12];
    const float* Wo   = (const float*)d_in[13];
    const float* bo   = (const float*)d_in[14];
    float* out = (float*)d_out;

    float *xq, *xk, *xv, *Q, *K, *V, *Q2, *O;
    cudaGetSymbolAddress((void**)&xq, g_xq);
    cudaGetSymbolAddress((void**)&xk, g_xk);
    cudaGetSymbolAddress((void**)&xv, g_xv);
    cudaGetSymbolAddress((void**)&Q,  g_Q);
    cudaGetSymbolAddress((void**)&K,  g_K);
    cudaGetSymbolAddress((void**)&V,  g_V);
    cudaGetSymbolAddress((void**)&Q2, g_Q2);
    cudaGetSymbolAddress((void**)&O,  g_O);

    static int attr_done = 0;
    if (!attr_done) {
        cudaFuncSetAttribute(attn_mma, cudaFuncAttributeMaxDynamicSharedMemorySize, ATTN_SMEM);
        attr_done = 1;
    }

    ln3_kernel<<<TOK, 256>>>(data, gk, bk, gq, bq, gv, bv, xq, xk, xv);

    dim3 ggrid(DD / 128, TOK / 128);            // (8, 32)
    gemm_mma<0,1><<<ggrid, 256>>>(xq, Wq, bq2, Q);
    gemm_mma<0,1><<<ggrid, 256>>>(xk, Wk, bk2, K);
    gemm_mma<0,1><<<ggrid, 256>>>(xv, Wv, bv2, V);

    dim3 agrid(SS / 64, BB * HH);               // (32, 32)
    attn_mma<<<agrid, 128, ATTN_SMEM>>>(Q,  K, K, Q2); // Hopfield update
    attn_mma<<<agrid, 128, ATTN_SMEM>>>(Q2, K, V, O);  // retrieval

    gemm_mma<1,0><<<ggrid, 256>>>(O, Wo, bo, out);
}

// round 3
// speedup vs baseline: 4.8954x; 1.1873x over previous
#include <cuda_runtime.h>
#include <math.h>

// Problem constants
#define BB   2
#define SS   2048
#define DD   1024
#define HH   16
#define HDIM 64
#define TOK  (BB*SS)           // 4096 rows
#define NSCALE 0.125f          // 1/sqrt(64)

// ---------------------------------------------------------------------------
// Scratch (static __device__ arrays; no allocation allowed)
// All intermediates are stored ALREADY tf32-rounded so tile loads can be bare
// cp.async (no cvt in the hot loops).
// ---------------------------------------------------------------------------
__device__ float g_xq[TOK*DD];
__device__ float g_xk[TOK*DD];
__device__ float g_xv[TOK*DD];
__device__ float g_Q [TOK*DD];   // head layout [B,H,S,HD]
__device__ float g_K [TOK*DD];
__device__ float g_V [TOK*DD];
__device__ float g_Q2[TOK*DD];
__device__ float g_O [TOK*DD];
__device__ float g_Wq[DD*DD];    // tf32-rounded weights
__device__ float g_Wk[DD*DD];
__device__ float g_Wv[DD*DD];
__device__ float g_Wo[DD*DD];

// ---------------------------------------------------------------------------
// helpers
// ---------------------------------------------------------------------------
__device__ __forceinline__ float tf32r(float x) {
    unsigned u;
    asm("cvt.rna.tf32.f32 %0, %1;" : "=r"(u) : "f"(x));
    return __uint_as_float(u);
}

__device__ __forceinline__ void mma8(float* d, const unsigned* a, unsigned b0, unsigned b1) {
    asm volatile(
        "mma.sync.aligned.m16n8k8.row.col.f32.tf32.tf32.f32 "
        "{%0,%1,%2,%3}, {%4,%5,%6,%7}, {%8,%9}, {%0,%1,%2,%3};"
        : "+f"(d[0]), "+f"(d[1]), "+f"(d[2]), "+f"(d[3])
        : "r"(a[0]), "r"(a[1]), "r"(a[2]), "r"(a[3]), "r"(b0), "r"(b1));
}

__device__ __forceinline__ void cpa16(unsigned dst, const void* src) {
    asm volatile("cp.async.cg.shared.global [%0], [%1], 16;" :: "r"(dst), "l"(src));
}
__device__ __forceinline__ void cpa_commit() {
    asm volatile("cp.async.commit_group;");
}
__device__ __forceinline__ void cpa_wait0() {
    asm volatile("cp.async.wait_group 0;");
}
__device__ __forceinline__ void cpa_wait1() {
    asm volatile("cp.async.wait_group 1;");
}

// ---------------------------------------------------------------------------
// Weight pre-round: dst = tf32(src), 4 floats/thread
// ---------------------------------------------------------------------------
__global__ __launch_bounds__(256) void roundw_kernel(
    const float* __restrict__ src, float* __restrict__ dst)
{
    int i = blockIdx.x * 256 + threadIdx.x;
    float4 v = ((const float4*)src)[i];
    ((float4*)dst)[i] = make_float4(tf32r(v.x), tf32r(v.y), tf32r(v.z), tf32r(v.w));
}

// ---------------------------------------------------------------------------
// Block reduction (256 threads)
// ---------------------------------------------------------------------------
__device__ __forceinline__ float blk_sum256(float v) {
    __shared__ float red[8];
    int lane = threadIdx.x & 31;
    int w    = threadIdx.x >> 5;
    #pragma unroll
    for (int o = 16; o > 0; o >>= 1) v += __shfl_xor_sync(0xffffffffu, v, o);
    __syncthreads();
    if (lane == 0) red[w] = v;
    __syncthreads();
    return red[0]+red[1]+red[2]+red[3]+red[4]+red[5]+red[6]+red[7];
}

// ---------------------------------------------------------------------------
// Fused triple LayerNorm (outputs tf32-rounded)
// ---------------------------------------------------------------------------
__global__ __launch_bounds__(256) void ln3_kernel(
    const float* __restrict__ data,
    const float* __restrict__ gk, const float* __restrict__ bk,
    const float* __restrict__ gq, const float* __restrict__ bq,
    const float* __restrict__ gv, const float* __restrict__ bv,
    float* __restrict__ xq, float* __restrict__ xk, float* __restrict__ xv)
{
    int row = blockIdx.x;
    int t   = threadIdx.x;
    const float4 x4 = ((const float4*)(data + (size_t)row * DD))[t];
    float s = x4.x + x4.y + x4.z + x4.w;
    float mean = blk_sum256(s) * (1.0f / DD);
    float d0 = x4.x - mean, d1 = x4.y - mean, d2 = x4.z - mean, d3 = x4.w - mean;
    float sq = d0*d0 + d1*d1 + d2*d2 + d3*d3;
    float var = blk_sum256(sq) * (1.0f / DD);
    float r = rsqrtf(var + 1e-5f);
    float n0 = d0*r, n1 = d1*r, n2 = d2*r, n3 = d3*r;

    float4 g4, b4, o4;
    size_t base = (size_t)row * DD;

    g4 = ((const float4*)gq)[t]; b4 = ((const float4*)bq)[t];
    o4 = make_float4(tf32r(n0*g4.x + b4.x), tf32r(n1*g4.y + b4.y),
                     tf32r(n2*g4.z + b4.z), tf32r(n3*g4.w + b4.w));
    ((float4*)(xq + base))[t] = o4;

    g4 = ((const float4*)gk)[t]; b4 = ((const float4*)bk)[t];
    o4 = make_float4(tf32r(n0*g4.x + b4.x), tf32r(n1*g4.y + b4.y),
                     tf32r(n2*g4.z + b4.z), tf32r(n3*g4.w + b4.w));
    ((float4*)(xk + base))[t] = o4;

    g4 = ((const float4*)gv)[t]; b4 = ((const float4*)bv)[t];
    o4 = make_float4(tf32r(n0*g4.x + b4.x), tf32r(n1*g4.y + b4.y),
                     tf32r(n2*g4.z + b4.z), tf32r(n3*g4.w + b4.w));
    ((float4*)(xv + base))[t] = o4;
}

// ---------------------------------------------------------------------------
// tf32 tensor-core GEMM, cp.async double-buffered.
// C[4096,1024] = A[4096,1024] @ W[1024,1024] + bias
// BM=128 BN=128 BK=16, 256 thr = 8 warps (2x4), warp tile 64x32.
// MODE_IN : 0 = A row-major;  1 = A head-layout gather
// MODE_OUT: 0 = C row-major;  1 = C head-layout scatter
// ROUND   : 1 = round outputs to tf32 (intermediates), 0 = full fp32 (final)
// ---------------------------------------------------------------------------
template<int MODE_IN, int MODE_OUT, int ROUND>
__global__ __launch_bounds__(256, 2) void gemm_mma(
    const float* __restrict__ A, const float* __restrict__ W,
    const float* __restrict__ bias, float* __restrict__ C)
{
    constexpr int BM = 128, BN = 128, BK = 16;
    constexpr int APAD = 20;    // A stage pitch (floats) — conflict-free + 16B rows
    constexpr int BPAD = 136;   // B stage pitch
    constexpr int ASZ = BM * APAD;
    constexpr int BSZ = BK * BPAD;
    __shared__ float As[2 * ASZ];
    __shared__ float Bs[2 * BSZ];

    int tid  = threadIdx.x;
    int lane = tid & 31;
    int w    = tid >> 5;
    int g    = lane >> 2;
    int t    = lane & 3;
    int wm   = (w >> 2) * 64;
    int wn   = (w & 3) * 32;
    int bm   = blockIdx.y * BM;
    int bn   = blockIdx.x * BN;

    int ar = tid >> 1;          // 0..127
    int ac = (tid & 1) * 8;     // 0 or 8
    int br = tid >> 4;          // 0..15
    int bc = (tid & 15) * 8;    // 0..120

    unsigned as_base = (unsigned)__cvta_generic_to_shared(As);
    unsigned bs_base = (unsigned)__cvta_generic_to_shared(Bs);

    float acc[4][4][4];
    #pragma unroll
    for (int i = 0; i < 4; i++)
        #pragma unroll
        for (int j = 0; j < 4; j++)
            #pragma unroll
            for (int q = 0; q < 4; q++) acc[i][j][q] = 0.f;

    // tile loader
    auto load_tile = [&](int it, int stg) {
        int kk = it * BK;
        int gm = bm + ar;
        int gk = kk + ac;
        const float* pa;
        if (MODE_IN == 0) {
            pa = &A[(size_t)gm * DD + gk];
        } else {
            int b  = gm >> 11, s2 = gm & (SS - 1);
            int h  = gk >> 6,  hd = gk & (HDIM - 1);
            pa = &A[(((size_t)(b*HH + h) * SS + s2) * HDIM) + hd];
        }
        unsigned da = as_base + (stg * ASZ + ar * APAD + ac) * 4;
        cpa16(da,      pa);
        cpa16(da + 16, pa + 4);
        const float* pb = &W[(size_t)(kk + br) * DD + bn + bc];
        unsigned db = bs_base + (stg * BSZ + br * BPAD + bc) * 4;
        cpa16(db,      pb);
        cpa16(db + 16, pb + 4);
    };

    constexpr int KITER = DD / BK;   // 64
    load_tile(0, 0);
    cpa_commit();

    for (int it = 0; it < KITER; it++) {
        int cur = it & 1;
        if (it + 1 < KITER) {
            load_tile(it + 1, cur ^ 1);
            cpa_commit();
            cpa_wait1();
        } else {
            cpa_wait0();
        }
        __syncthreads();

        const float* Ab = As + cur * ASZ;
        const float* Bb = Bs + cur * BSZ;
        #pragma unroll
        for (int ks = 0; ks < 2; ks++) {
            int k0 = ks * 8;
            unsigned af[4][4], bf[4][2];
            #pragma unroll
            for (int mi = 0; mi < 4; mi++) {
                int r = wm + mi * 16 + g;
                af[mi][0] = __float_as_uint(Ab[(r    ) * APAD + k0 + t    ]);
                af[mi][1] = __float_as_uint(Ab[(r + 8) * APAD + k0 + t    ]);
                af[mi][2] = __float_as_uint(Ab[(r    ) * APAD + k0 + t + 4]);
                af[mi][3] = __float_as_uint(Ab[(r + 8) * APAD + k0 + t + 4]);
            }
            #pragma unroll
            for (int ni = 0; ni < 4; ni++) {
                int c = wn + ni * 8 + g;
                bf[ni][0] = __float_as_uint(Bb[(k0 + t    ) * BPAD + c]);
                bf[ni][1] = __float_as_uint(Bb[(k0 + t + 4) * BPAD + c]);
            }
            #pragma unroll
            for (int mi = 0; mi < 4; mi++)
                #pragma unroll
                for (int ni = 0; ni < 4; ni++)
                    mma8(acc[mi][ni], af[mi], bf[ni][0], bf[ni][1]);
        }
        __syncthreads();
    }

    // ---- epilogue ----
    #pragma unroll
    for (int mi = 0; mi < 4; mi++) {
        #pragma unroll
        for (int ni = 0; ni < 4; ni++) {
            int row = bm + wm + mi * 16 + g;
            int col = bn + wn + ni * 8 + 2 * t;
            float2 bia = *(const float2*)&bias[col];
            float2 v0, v1;
            if (ROUND) {
                v0 = make_float2(tf32r(acc[mi][ni][0] + bia.x), tf32r(acc[mi][ni][1] + bia.y));
                v1 = make_float2(tf32r(acc[mi][ni][2] + bia.x), tf32r(acc[mi][ni][3] + bia.y));
            } else {
                v0 = make_float2(acc[mi][ni][0] + bia.x, acc[mi][ni][1] + bia.y);
                v1 = make_float2(acc[mi][ni][2] + bia.x, acc[mi][ni][3] + bia.y);
            }
            if (MODE_OUT == 0) {
                *(float2*)&C[(size_t)row * DD + col]       = v0;
                *(float2*)&C[(size_t)(row + 8) * DD + col] = v1;
            } else {
                int h = col >> 6, hd = col & (HDIM - 1);
                int b0i = row >> 11,       s0 = row & (SS - 1);
                int b1i = (row + 8) >> 11, s1 = (row + 8) & (SS - 1);
                *(float2*)&C[((size_t)(b0i*HH + h) * SS + s0) * HDIM + hd] = v0;
                *(float2*)&C[((size_t)(b1i*HH + h) * SS + s1) * HDIM + hd] = v1;
            }
        }
    }
}

// ---------------------------------------------------------------------------
// Flash attention, tf32 mma, cp.async double-buffered K/V tiles.
// Out = tf32_round( softmax(NSCALE * Qin Kin^T) @ Vin )
// grid = (S/64, B*H); 128 threads = 4 warps; warp owns 16 query rows.
// Dyn smem: Ks[2][64][68] | Vs[2][64][72] | Ps[4][16][68]
// ---------------------------------------------------------------------------
#define KSP 68
#define VSP 72
#define PSP 68
#define KTSZ (64*KSP)
#define VTSZ (64*VSP)
#define ATTN_SMEM ((2*KTSZ + 2*VTSZ + 4*16*PSP) * 4)

__global__ __launch_bounds__(128) void attn_mma(
    const float* __restrict__ Qin, const float* __restrict__ Kin,
    const float* __restrict__ Vin, float* __restrict__ Out)
{
    extern __shared__ float sm[];
    float* Ks = sm;                          // [2][64][KSP]
    float* Vs = sm + 2 * KTSZ;               // [2][64][VSP]
    float* Ps = sm + 2 * KTSZ + 2 * VTSZ;    // [4][16][PSP]
    unsigned ks_base = (unsigned)__cvta_generic_to_shared(Ks);
    unsigned vs_base = (unsigned)__cvta_generic_to_shared(Vs);

    int lane = threadIdx.x & 31;
    int w    = threadIdx.x >> 5;
    int g    = lane >> 2;
    int t    = lane & 3;
    int bh   = blockIdx.y;
    int q0   = blockIdx.x * 64;
    size_t base = (size_t)bh * SS * HDIM;

    // Q fragments (already tf32; *NSCALE is exact power-of-2)
    unsigned qa[8][4];
    {
        const float* Qp = Qin + base;
        int r0 = q0 + w * 16 + g;
        #pragma unroll
        for (int ks = 0; ks < 8; ks++) {
            qa[ks][0] = __float_as_uint(Qp[(size_t)r0     * HDIM + ks*8 + t    ] * NSCALE);
            qa[ks][1] = __float_as_uint(Qp[(size_t)(r0+8) * HDIM + ks*8 + t    ] * NSCALE);
            qa[ks][2] = __float_as_uint(Qp[(size_t)r0     * HDIM + ks*8 + t + 4] * NSCALE);
            qa[ks][3] = __float_as_uint(Qp[(size_t)(r0+8) * HDIM + ks*8 + t + 4] * NSCALE);
        }
    }

    float o[8][4];
    #pragma unroll
    for (int j = 0; j < 8; j++)
        #pragma unroll
        for (int q = 0; q < 4; q++) o[j][q] = 0.f;
    float m0 = -1e30f, m1 = -1e30f, l0 = 0.f, l1 = 0.f;

    int lrow = threadIdx.x >> 1;          // 0..63
    int lcol = (threadIdx.x & 1) * 32;    // 0 or 32

    auto load_kv = [&](int kt, int stg) {
        const float* Kp = Kin + base + (size_t)(kt*64 + lrow) * HDIM + lcol;
        const float* Vp = Vin + base + (size_t)(kt*64 + lrow) * HDIM + lcol;
        unsigned kd = ks_base + (stg * KTSZ + lrow * KSP + lcol) * 4;
        unsigned vd = vs_base + (stg * VTSZ + lrow * VSP + lcol) * 4;
        #pragma unroll
        for (int i = 0; i < 8; i++) cpa16(kd + i*16, Kp + i*4);
        #pragma unroll
        for (int i = 0; i < 8; i++) cpa16(vd + i*16, Vp + i*4);
    };

    constexpr int NT = SS / 64;   // 32
    load_kv(0, 0);
    cpa_commit();

    for (int kt = 0; kt < NT; kt++) {
        int cur = kt & 1;
        if (kt + 1 < NT) {
            load_kv(kt + 1, cur ^ 1);
            cpa_commit();
            cpa_wait1();
        } else {
            cpa_wait0();
        }
        __syncthreads();

        const float* Kb = Ks + cur * KTSZ;
        const float* Vb = Vs + cur * VTSZ;

        // ---- S = Q K^T  (per warp 16x64) ----
        float s[8][4];
        #pragma unroll
        for (int n = 0; n < 8; n++)
            #pragma unroll
            for (int q = 0; q < 4; q++) s[n][q] = 0.f;

        #pragma unroll
        for (int ks = 0; ks < 8; ks++) {
            #pragma unroll
            for (int n = 0; n < 8; n++) {
                unsigned b0 = __float_as_uint(Kb[(n*8 + g) * KSP + ks*8 + t    ]);
                unsigned b1 = __float_as_uint(Kb[(n*8 + g) * KSP + ks*8 + t + 4]);
                mma8(s[n], qa[ks], b0, b1);
            }
        }

        // ---- online softmax ----
        float tm0 = -1e30f, tm1 = -1e30f;
        #pragma unroll
        for (int n = 0; n < 8; n++) {
            tm0 = fmaxf(tm0, fmaxf(s[n][0], s[n][1]));
            tm1 = fmaxf(tm1, fmaxf(s[n][2], s[n][3]));
        }
        tm0 = fmaxf(tm0, __shfl_xor_sync(0xffffffffu, tm0, 1));
        tm0 = fmaxf(tm0, __shfl_xor_sync(0xffffffffu, tm0, 2));
        tm1 = fmaxf(tm1, __shfl_xor_sync(0xffffffffu, tm1, 1));
        tm1 = fmaxf(tm1, __shfl_xor_sync(0xffffffffu, tm1, 2));

        float nm0 = fmaxf(m0, tm0), nm1 = fmaxf(m1, tm1);
        float c0 = __expf(m0 - nm0), c1 = __expf(m1 - nm1);
        m0 = nm0; m1 = nm1;

        float ps0 = 0.f, ps1 = 0.f;
        float* Pw = Ps + w * 16 * PSP;
        #pragma unroll
        for (int n = 0; n < 8; n++) {
            float p0 = __expf(s[n][0] - m0);
            float p1 = __expf(s[n][1] - m0);
            float p2 = __expf(s[n][2] - m1);
            float p3 = __expf(s[n][3] - m1);
            ps0 += p0 + p1;
            ps1 += p2 + p3;
            Pw[ g      * PSP + n*8 + 2*t    ] = tf32r(p0);
            Pw[ g      * PSP + n*8 + 2*t + 1] = tf32r(p1);
            Pw[(g + 8) * PSP + n*8 + 2*t    ] = tf32r(p2);
            Pw[(g + 8) * PSP + n*8 + 2*t + 1] = tf32r(p3);
        }
        ps0 += __shfl_xor_sync(0xffffffffu, ps0, 1);
        ps0 += __shfl_xor_sync(0xffffffffu, ps0, 2);
        ps1 += __shfl_xor_sync(0xffffffffu, ps1, 1);
        ps1 += __shfl_xor_sync(0xffffffffu, ps1, 2);
        l0 = l0 * c0 + ps0;
        l1 = l1 * c1 + ps1;
        #pragma unroll
        for (int j = 0; j < 8; j++) {
            o[j][0] *= c0; o[j][1] *= c0;
            o[j][2] *= c1; o[j][3] *= c1;
        }
        __syncwarp();

        // ---- O += P V  (per warp 16x64) ----
        #pragma unroll
        for (int ks = 0; ks < 8; ks++) {
            unsigned pa[4];
            pa[0] = __float_as_uint(Pw[ g      * PSP + ks*8 + t    ]);
            pa[1] = __float_as_uint(Pw[(g + 8) * PSP + ks*8 + t    ]);
            pa[2] = __float_as_uint(Pw[ g      * PSP + ks*8 + t + 4]);
            pa[3] = __float_as_uint(Pw[(g + 8) * PSP + ks*8 + t + 4]);
            #pragma unroll
            for (int j = 0; j < 8; j++) {
                unsigned b0 = __float_as_uint(Vb[(ks*8 + t    ) * VSP + j*8 + g]);
                unsigned b1 = __float_as_uint(Vb[(ks*8 + t + 4) * VSP + j*8 + g]);
                mma8(o[j], pa, b0, b1);
            }
        }
        __syncthreads();
    }

    // ---- epilogue (tf32-rounded: consumed by mma downstream) ----
    float inv0 = 1.f / l0, inv1 = 1.f / l1;
    int r0 = q0 + w * 16 + g;
    float* Op = Out + base;
    #pragma unroll
    for (int j = 0; j < 8; j++) {
        *(float2*)&Op[(size_t)r0     * HDIM + j*8 + 2*t] =
            make_float2(tf32r(o[j][0] * inv0), tf32r(o[j][1] * inv0));
        *(float2*)&Op[(size_t)(r0+8) * HDIM + j*8 + 2*t] =
            make_float2(tf32r(o[j][2] * inv1), tf32r(o[j][3] * inv1));
    }
}

// ---------------------------------------------------------------------------
// Launch
// ---------------------------------------------------------------------------
extern "C" void kernel_launch(void* const* d_in, const int* in_sizes, int n_in,
                              void* d_out, int out_size)
{
    const float* data = (const float*)d_in[0];
    const float* gk   = (const float*)d_in[1];
    const float* bk   = (const float*)d_in[2];
    const float* gq   = (const float*)d_in[3];
    const float* bq   = (const float*)d_in[4];
    const float* gv   = (const float*)d_in[5];
    const float* bv   = (const float*)d_in[6];
    const float* Wq   = (const float*)d_in[7];
    const float* bq2  = (const float*)d_in[8];
    const float* Wk   = (const float*)d_in[9];
    const float* bk2  = (const float*)d_in[10];
    const float* Wv   = (const float*)d_in[11];
    const float* bv2  = (const float*)d_in[12];
    const float* Wo   = (const float*)d_in[13];
    const float* bo   = (const float*)d_in[14];
    float* out = (float*)d_out;

    float *xq, *xk, *xv, *Q, *K, *V, *Q2, *O, *rWq, *rWk, *rWv, *rWo;
    cudaGetSymbolAddress((void**)&xq, g_xq);
    cudaGetSymbolAddress((void**)&xk, g_xk);
    cudaGetSymbolAddress((void**)&xv, g_xv);
    cudaGetSymbolAddress((void**)&Q,  g_Q);
    cudaGetSymbolAddress((void**)&K,  g_K);
    cudaGetSymbolAddress((void**)&V,  g_V);
    cudaGetSymbolAddress((void**)&Q2, g_Q2);
    cudaGetSymbolAddress((void**)&O,  g_O);
    cudaGetSymbolAddress((void**)&rWq, g_Wq);
    cudaGetSymbolAddress((void**)&rWk, g_Wk);
    cudaGetSymbolAddress((void**)&rWv, g_Wv);
    cudaGetSymbolAddress((void**)&rWo, g_Wo);

    static int attr_done = 0;
    if (!attr_done) {
        cudaFuncSetAttribute(attn_mma, cudaFuncAttributeMaxDynamicSharedMemorySize, ATTN_SMEM);
        attr_done = 1;
    }

    int wblk = DD * DD / 4 / 256;   // 1024
    roundw_kernel<<<wblk, 256>>>(Wq, rWq);
    roundw_kernel<<<wblk, 256>>>(Wk, rWk);
    roundw_kernel<<<wblk, 256>>>(Wv, rWv);
    roundw_kernel<<<wblk, 256>>>(Wo, rWo);

    ln3_kernel<<<TOK, 256>>>(data, gk, bk, gq, bq, gv, bv, xq, xk, xv);

    dim3 ggrid(DD / 128, TOK / 128);            // (8, 32)
    gemm_mma<0,1,1><<<ggrid, 256>>>(xq, rWq, bq2, Q);
    gemm_mma<0,1,1><<<ggrid, 256>>>(xk, rWk, bk2, K);
    gemm_mma<0,1,1><<<ggrid, 256>>>(xv, rWv, bv2, V);

    dim3 agrid(SS / 64, BB * HH);               // (32, 32)
    attn_mma<<<agrid, 128, ATTN_SMEM>>>(Q,  K, K, Q2); // Hopfield update
    attn_mma<<<agrid, 128, ATTN_SMEM>>>(Q2, K, V, O);  // retrieval

    gemm_mma<1,0,0><<<ggrid, 256>>>(O, rWo, bo, out);
}

// round 4
// speedup vs baseline: 5.5593x; 1.1356x over previous
#include <cuda_runtime.h>
#include <math.h>

// Problem constants
#define BB   2
#define SS   2048
#define DD   1024
#define HH   16
#define HDIM 64
#define TOK  (BB*SS)           // 4096 rows
#define NSCALE 0.125f          // 1/sqrt(64)

// ---------------------------------------------------------------------------
// Scratch (static __device__ arrays; no allocation allowed)
// All intermediates stored ALREADY tf32-rounded -> bare cp.async tile loads.
// ---------------------------------------------------------------------------
__device__ float g_xq[TOK*DD];
__device__ float g_xk[TOK*DD];
__device__ float g_xv[TOK*DD];
__device__ float g_Q [TOK*DD];   // head layout [B,H,S,HD]
__device__ float g_K [TOK*DD];
__device__ float g_V [TOK*DD];
__device__ float g_Q2[TOK*DD];
__device__ float g_O [TOK*DD];
__device__ float g_Wq[DD*DD];    // tf32-rounded weights
__device__ float g_Wk[DD*DD];
__device__ float g_Wv[DD*DD];
__device__ float g_Wo[DD*DD];

// ---------------------------------------------------------------------------
// helpers
// ---------------------------------------------------------------------------
__device__ __forceinline__ float tf32r(float x) {
    unsigned u;
    asm("cvt.rna.tf32.f32 %0, %1;" : "=r"(u) : "f"(x));
    return __uint_as_float(u);
}

__device__ __forceinline__ void mma8(float* d, const unsigned* a, unsigned b0, unsigned b1) {
    asm volatile(
        "mma.sync.aligned.m16n8k8.row.col.f32.tf32.tf32.f32 "
        "{%0,%1,%2,%3}, {%4,%5,%6,%7}, {%8,%9}, {%0,%1,%2,%3};"
        : "+f"(d[0]), "+f"(d[1]), "+f"(d[2]), "+f"(d[3])
        : "r"(a[0]), "r"(a[1]), "r"(a[2]), "r"(a[3]), "r"(b0), "r"(b1));
}

__device__ __forceinline__ void cpa16(unsigned dst, const void* src) {
    asm volatile("cp.async.cg.shared.global [%0], [%1], 16;" :: "r"(dst), "l"(src));
}
__device__ __forceinline__ void cpa_commit() {
    asm volatile("cp.async.commit_group;");
}
__device__ __forceinline__ void cpa_wait0() {
    asm volatile("cp.async.wait_group 0;");
}
__device__ __forceinline__ void cpa_wait1() {
    asm volatile("cp.async.wait_group 1;");
}

// ---------------------------------------------------------------------------
// Weight pre-round
// ---------------------------------------------------------------------------
__global__ __launch_bounds__(256) void roundw_kernel(
    const float* __restrict__ src, float* __restrict__ dst)
{
    int i = blockIdx.x * 256 + threadIdx.x;
    float4 v = ((const float4*)src)[i];
    ((float4*)dst)[i] = make_float4(tf32r(v.x), tf32r(v.y), tf32r(v.z), tf32r(v.w));
}

// ---------------------------------------------------------------------------
// Block reduction (256 threads)
// ---------------------------------------------------------------------------
__device__ __forceinline__ float blk_sum256(float v) {
    __shared__ float red[8];
    int lane = threadIdx.x & 31;
    int w    = threadIdx.x >> 5;
    #pragma unroll
    for (int o = 16; o > 0; o >>= 1) v += __shfl_xor_sync(0xffffffffu, v, o);
    __syncthreads();
    if (lane == 0) red[w] = v;
    __syncthreads();
    return red[0]+red[1]+red[2]+red[3]+red[4]+red[5]+red[6]+red[7];
}

// ---------------------------------------------------------------------------
// Fused triple LayerNorm (outputs tf32-rounded)
// ---------------------------------------------------------------------------
__global__ __launch_bounds__(256) void ln3_kernel(
    const float* __restrict__ data,
    const float* __restrict__ gk, const float* __restrict__ bk,
    const float* __restrict__ gq, const float* __restrict__ bq,
    const float* __restrict__ gv, const float* __restrict__ bv,
    float* __restrict__ xq, float* __restrict__ xk, float* __restrict__ xv)
{
    int row = blockIdx.x;
    int t   = threadIdx.x;
    const float4 x4 = ((const float4*)(data + (size_t)row * DD))[t];
    float s = x4.x + x4.y + x4.z + x4.w;
    float mean = blk_sum256(s) * (1.0f / DD);
    float d0 = x4.x - mean, d1 = x4.y - mean, d2 = x4.z - mean, d3 = x4.w - mean;
    float sq = d0*d0 + d1*d1 + d2*d2 + d3*d3;
    float var = blk_sum256(sq) * (1.0f / DD);
    float r = rsqrtf(var + 1e-5f);
    float n0 = d0*r, n1 = d1*r, n2 = d2*r, n3 = d3*r;

    float4 g4, b4, o4;
    size_t base = (size_t)row * DD;

    g4 = ((const float4*)gq)[t]; b4 = ((const float4*)bq)[t];
    o4 = make_float4(tf32r(n0*g4.x + b4.x), tf32r(n1*g4.y + b4.y),
                     tf32r(n2*g4.z + b4.z), tf32r(n3*g4.w + b4.w));
    ((float4*)(xq + base))[t] = o4;

    g4 = ((const float4*)gk)[t]; b4 = ((const float4*)bk)[t];
    o4 = make_float4(tf32r(n0*g4.x + b4.x), tf32r(n1*g4.y + b4.y),
                     tf32r(n2*g4.z + b4.z), tf32r(n3*g4.w + b4.w));
    ((float4*)(xk + base))[t] = o4;

    g4 = ((const float4*)gv)[t]; b4 = ((const float4*)bv)[t];
    o4 = make_float4(tf32r(n0*g4.x + b4.x), tf32r(n1*g4.y + b4.y),
                     tf32r(n2*g4.z + b4.z), tf32r(n3*g4.w + b4.w));
    ((float4*)(xv + base))[t] = o4;
}

// ---------------------------------------------------------------------------
// tf32 tensor-core GEMM, cp.async double-buffered, BK=32.
// C[4096,1024] = A[4096,1024] @ W[1024,1024] + bias
// BM=128 BN=128 BK=32, 256 thr = 8 warps (2x4), warp tile 64x32.
// ---------------------------------------------------------------------------
template<int MODE_IN, int MODE_OUT, int ROUND>
__global__ __launch_bounds__(256, 2) void gemm_mma(
    const float* __restrict__ A, const float* __restrict__ W,
    const float* __restrict__ bias, float* __restrict__ C)
{
    constexpr int BM = 128, BN = 128, BK = 32;
    constexpr int APAD = 36;    // A stage pitch (floats)
    constexpr int BPAD = 136;   // B stage pitch
    constexpr int ASZ = BM * APAD;   // 4608
    constexpr int BSZ = BK * BPAD;   // 4352
    __shared__ float As[2 * ASZ];
    __shared__ float Bs[2 * BSZ];

    int tid  = threadIdx.x;
    int lane = tid & 31;
    int w    = tid >> 5;
    int g    = lane >> 2;
    int t    = lane & 3;
    int wm   = (w >> 2) * 64;
    int wn   = (w & 3) * 32;
    int bm   = blockIdx.y * BM;
    int bn   = blockIdx.x * BN;

    int ar = tid >> 1;          // 0..127
    int ac = (tid & 1) * 16;    // 0 or 16
    int br = tid >> 3;          // 0..31
    int bc = (tid & 7) * 16;    // 0..112

    unsigned as_base = (unsigned)__cvta_generic_to_shared(As);
    unsigned bs_base = (unsigned)__cvta_generic_to_shared(Bs);

    float acc[4][4][4];
    #pragma unroll
    for (int i = 0; i < 4; i++)
        #pragma unroll
        for (int j = 0; j < 4; j++)
            #pragma unroll
            for (int q = 0; q < 4; q++) acc[i][j][q] = 0.f;

    auto load_tile = [&](int it, int stg) {
        int kk = it * BK;
        int gm = bm + ar;
        int gk = kk + ac;
        const float* pa;
        if (MODE_IN == 0) {
            pa = &A[(size_t)gm * DD + gk];
        } else {
            int b  = gm >> 11, s2 = gm & (SS - 1);
            int h  = gk >> 6,  hd = gk & (HDIM - 1);
            pa = &A[(((size_t)(b*HH + h) * SS + s2) * HDIM) + hd];
        }
        unsigned da = as_base + (stg * ASZ + ar * APAD + ac) * 4;
        #pragma unroll
        for (int i = 0; i < 4; i++) cpa16(da + i*16, pa + i*4);
        const float* pb = &W[(size_t)(kk + br) * DD + bn + bc];
        unsigned db = bs_base + (stg * BSZ + br * BPAD + bc) * 4;
        #pragma unroll
        for (int i = 0; i < 4; i++) cpa16(db + i*16, pb + i*4);
    };

    constexpr int KITER = DD / BK;   // 32
    load_tile(0, 0);
    cpa_commit();

    for (int it = 0; it < KITER; it++) {
        int cur = it & 1;
        if (it + 1 < KITER) {
            load_tile(it + 1, cur ^ 1);
            cpa_commit();
            cpa_wait1();
        } else {
            cpa_wait0();
        }
        __syncthreads();

        const float* Ab = As + cur * ASZ;
        const float* Bb = Bs + cur * BSZ;
        #pragma unroll
        for (int ks = 0; ks < 4; ks++) {
            int k0 = ks * 8;
            unsigned af[4][4], bf[4][2];
            #pragma unroll
            for (int mi = 0; mi < 4; mi++) {
                int r = wm + mi * 16 + g;
                af[mi][0] = __float_as_uint(Ab[(r    ) * APAD + k0 + t    ]);
                af[mi][1] = __float_as_uint(Ab[(r + 8) * APAD + k0 + t    ]);
                af[mi][2] = __float_as_uint(Ab[(r    ) * APAD + k0 + t + 4]);
                af[mi][3] = __float_as_uint(Ab[(r + 8) * APAD + k0 + t + 4]);
            }
            #pragma unroll
            for (int ni = 0; ni < 4; ni++) {
                int c = wn + ni * 8 + g;
                bf[ni][0] = __float_as_uint(Bb[(k0 + t    ) * BPAD + c]);
                bf[ni][1] = __float_as_uint(Bb[(k0 + t + 4) * BPAD + c]);
            }
            #pragma unroll
            for (int mi = 0; mi < 4; mi++)
                #pragma unroll
                for (int ni = 0; ni < 4; ni++)
                    mma8(acc[mi][ni], af[mi], bf[ni][0], bf[ni][1]);
        }
        __syncthreads();
    }

    // ---- epilogue ----
    #pragma unroll
    for (int mi = 0; mi < 4; mi++) {
        #pragma unroll
        for (int ni = 0; ni < 4; ni++) {
            int row = bm + wm + mi * 16 + g;
            int col = bn + wn + ni * 8 + 2 * t;
            float2 bia = *(const float2*)&bias[col];
            float2 v0, v1;
            if (ROUND) {
                v0 = make_float2(tf32r(acc[mi][ni][0] + bia.x), tf32r(acc[mi][ni][1] + bia.y));
                v1 = make_float2(tf32r(acc[mi][ni][2] + bia.x), tf32r(acc[mi][ni][3] + bia.y));
            } else {
                v0 = make_float2(acc[mi][ni][0] + bia.x, acc[mi][ni][1] + bia.y);
                v1 = make_float2(acc[mi][ni][2] + bia.x, acc[mi][ni][3] + bia.y);
            }
            if (MODE_OUT == 0) {
                *(float2*)&C[(size_t)row * DD + col]       = v0;
                *(float2*)&C[(size_t)(row + 8) * DD + col] = v1;
            } else {
                int h = col >> 6, hd = col & (HDIM - 1);
                int b0i = row >> 11,       s0 = row & (SS - 1);
                int b1i = (row + 8) >> 11, s1 = (row + 8) & (SS - 1);
                *(float2*)&C[((size_t)(b0i*HH + h) * SS + s0) * HDIM + hd] = v0;
                *(float2*)&C[((size_t)(b1i*HH + h) * SS + s1) * HDIM + hd] = v1;
            }
        }
    }
}

// ---------------------------------------------------------------------------
// Flash attention, tf32 mma, cp.async double-buffered K/V tiles.
// 256 threads = 8 warps; CTA covers 128 queries (16 per warp), K-tile 64.
// Dyn smem: Ks[2][64][68] | Vs[2][64][72] | Ps[8][16][68]  (~104 KB)
// ---------------------------------------------------------------------------
#define KSP 68
#define VSP 72
#define PSP 68
#define KTSZ (64*KSP)
#define VTSZ (64*VSP)
#define ATTN_SMEM ((2*KTSZ + 2*VTSZ + 8*16*PSP) * 4)

__global__ __launch_bounds__(256, 2) void attn_mma(
    const float* __restrict__ Qin, const float* __restrict__ Kin,
    const float* __restrict__ Vin, float* __restrict__ Out)
{
    extern __shared__ float sm[];
    float* Ks = sm;                          // [2][64][KSP]
    float* Vs = sm + 2 * KTSZ;               // [2][64][VSP]
    float* Ps = sm + 2 * KTSZ + 2 * VTSZ;    // [8][16][PSP]
    unsigned ks_base = (unsigned)__cvta_generic_to_shared(Ks);
    unsigned vs_base = (unsigned)__cvta_generic_to_shared(Vs);

    int tid  = threadIdx.x;
    int lane = tid & 31;
    int w    = tid >> 5;     // 0..7
    int g    = lane >> 2;
    int t    = lane & 3;
    int bh   = blockIdx.y;
    int q0   = blockIdx.x * 128;
    size_t base = (size_t)bh * SS * HDIM;

    // Q fragments (already tf32; *NSCALE exact power-of-2)
    unsigned qa[8][4];
    {
        const float* Qp = Qin + base;
        int r0 = q0 + w * 16 + g;
        #pragma unroll
        for (int ks = 0; ks < 8; ks++) {
            qa[ks][0] = __float_as_uint(Qp[(size_t)r0     * HDIM + ks*8 + t    ] * NSCALE);
            qa[ks][1] = __float_as_uint(Qp[(size_t)(r0+8) * HDIM + ks*8 + t    ] * NSCALE);
            qa[ks][2] = __float_as_uint(Qp[(size_t)r0     * HDIM + ks*8 + t + 4] * NSCALE);
            qa[ks][3] = __float_as_uint(Qp[(size_t)(r0+8) * HDIM + ks*8 + t + 4] * NSCALE);
        }
    }

    float o[8][4];
    #pragma unroll
    for (int j = 0; j < 8; j++)
        #pragma unroll
        for (int q = 0; q < 4; q++) o[j][q] = 0.f;
    float m0 = -1e30f, m1 = -1e30f, l0 = 0.f, l1 = 0.f;

    // cooperative loader: 256 threads, 64x64 tile -> 16 floats/thread
    int lrow = tid >> 2;          // 0..63
    int lcol = (tid & 3) * 16;    // 0,16,32,48

    auto load_kv = [&](int kt, int stg) {
        const float* Kp = Kin + base + (size_t)(kt*64 + lrow) * HDIM + lcol;
        const float* Vp = Vin + base + (size_t)(kt*64 + lrow) * HDIM + lcol;
        unsigned kd = ks_base + (stg * KTSZ + lrow * KSP + lcol) * 4;
        unsigned vd = vs_base + (stg * VTSZ + lrow * VSP + lcol) * 4;
        #pragma unroll
        for (int i = 0; i < 4; i++) cpa16(kd + i*16, Kp + i*4);
        #pragma unroll
        for (int i = 0; i < 4; i++) cpa16(vd + i*16, Vp + i*4);
    };

    constexpr int NT = SS / 64;   // 32
    load_kv(0, 0);
    cpa_commit();

    for (int kt = 0; kt < NT; kt++) {
        int cur = kt & 1;
        if (kt + 1 < NT) {
            load_kv(kt + 1, cur ^ 1);
            cpa_commit();
            cpa_wait1();
        } else {
            cpa_wait0();
        }
        __syncthreads();

        const float* Kb = Ks + cur * KTSZ;
        const float* Vb = Vs + cur * VTSZ;

        // ---- S = Q K^T  (per warp 16x64) ----
        float s[8][4];
        #pragma unroll
        for (int n = 0; n < 8; n++)
            #pragma unroll
            for (int q = 0; q < 4; q++) s[n][q] = 0.f;

        #pragma unroll
        for (int ks = 0; ks < 8; ks++) {
            #pragma unroll
            for (int n = 0; n < 8; n++) {
                unsigned b0 = __float_as_uint(Kb[(n*8 + g) * KSP + ks*8 + t    ]);
                unsigned b1 = __float_as_uint(Kb[(n*8 + g) * KSP + ks*8 + t + 4]);
                mma8(s[n], qa[ks], b0, b1);
            }
        }

        // ---- online softmax ----
        float tm0 = -1e30f, tm1 = -1e30f;
        #pragma unroll
        for (int n = 0; n < 8; n++) {
            tm0 = fmaxf(tm0, fmaxf(s[n][0], s[n][1]));
            tm1 = fmaxf(tm1, fmaxf(s[n][2], s[n][3]));
        }
        tm0 = fmaxf(tm0, __shfl_xor_sync(0xffffffffu, tm0, 1));
        tm0 = fmaxf(tm0, __shfl_xor_sync(0xffffffffu, tm0, 2));
        tm1 = fmaxf(tm1, __shfl_xor_sync(0xffffffffu, tm1, 1));
        tm1 = fmaxf(tm1, __shfl_xor_sync(0xffffffffu, tm1, 2));

        float nm0 = fmaxf(m0, tm0), nm1 = fmaxf(m1, tm1);
        float c0 = __expf(m0 - nm0), c1 = __expf(m1 - nm1);
        m0 = nm0; m1 = nm1;

        float ps0 = 0.f, ps1 = 0.f;
        float* Pw = Ps + w * 16 * PSP;
        #pragma unroll
        for (int n = 0; n < 8; n++) {
            float p0 = __expf(s[n][0] - m0);
            float p1 = __expf(s[n][1] - m0);
            float p2 = __expf(s[n][2] - m1);
            float p3 = __expf(s[n][3] - m1);
            ps0 += p0 + p1;
            ps1 += p2 + p3;
            Pw[ g      * PSP + n*8 + 2*t    ] = tf32r(p0);
            Pw[ g      * PSP + n*8 + 2*t + 1] = tf32r(p1);
            Pw[(g + 8) * PSP + n*8 + 2*t    ] = tf32r(p2);
            Pw[(g + 8) * PSP + n*8 + 2*t + 1] = tf32r(p3);
        }
        ps0 += __shfl_xor_sync(0xffffffffu, ps0, 1);
        ps0 += __shfl_xor_sync(0xffffffffu, ps0, 2);
        ps1 += __shfl_xor_sync(0xffffffffu, ps1, 1);
        ps1 += __shfl_xor_sync(0xffffffffu, ps1, 2);
        l0 = l0 * c0 + ps0;
        l1 = l1 * c1 + ps1;
        #pragma unroll
        for (int j = 0; j < 8; j++) {
            o[j][0] *= c0; o[j][1] *= c0;
            o[j][2] *= c1; o[j][3] *= c1;
        }
        __syncwarp();

        // ---- O += P V  (per warp 16x64) ----
        #pragma unroll
        for (int ks = 0; ks < 8; ks++) {
            unsigned pa[4];
            pa[0] = __float_as_uint(Pw[ g      * PSP + ks*8 + t    ]);
            pa[1] = __float_as_uint(Pw[(g + 8) * PSP + ks*8 + t    ]);
            pa[2] = __float_as_uint(Pw[ g      * PSP + ks*8 + t + 4]);
            pa[3] = __float_as_uint(Pw[(g + 8) * PSP + ks*8 + t + 4]);
            #pragma unroll
            for (int j = 0; j < 8; j++) {
                unsigned b0 = __float_as_uint(Vb[(ks*8 + t    ) * VSP + j*8 + g]);
                unsigned b1 = __float_as_uint(Vb[(ks*8 + t + 4) * VSP + j*8 + g]);
                mma8(o[j], pa, b0, b1);
            }
        }
        __syncthreads();
    }

    // ---- epilogue (tf32-rounded: consumed by mma downstream) ----
    float inv0 = 1.f / l0, inv1 = 1.f / l1;
    int r0 = q0 + w * 16 + g;
    float* Op = Out + base;
    #pragma unroll
    for (int j = 0; j < 8; j++) {
        *(float2*)&Op[(size_t)r0     * HDIM + j*8 + 2*t] =
            make_float2(tf32r(o[j][0] * inv0), tf32r(o[j][1] * inv0));
        *(float2*)&Op[(size_t)(r0+8) * HDIM + j*8 + 2*t] =
            make_float2(tf32r(o[j][2] * inv1), tf32r(o[j][3] * inv1));
    }
}

// ---------------------------------------------------------------------------
// Launch
// ---------------------------------------------------------------------------
extern "C" void kernel_launch(void* const* d_in, const int* in_sizes, int n_in,
                              void* d_out, int out_size)
{
    const float* data = (const float*)d_in[0];
    const float* gk   = (const float*)d_in[1];
    const float* bk   = (const float*)d_in[2];
    const float* gq   = (const float*)d_in[3];
    const float* bq   = (const float*)d_in[4];
    const float* gv   = (const float*)d_in[5];
    const float* bv   = (const float*)d_in[6];
    const float* Wq   = (const float*)d_in[7];
    const float* bq2  = (const float*)d_in[8];
    const float* Wk   = (const float*)d_in[9];
    const float* bk2  = (const float*)d_in[10];
    const float* Wv   = (const float*)d_in[11];
    const float* bv2  = (const float*)d_in[12];
    const float* Wo   = (const float*)d_in[13];
    const float* bo   = (const float*)d_in[14];
    float* out = (float*)d_out;

    float *xq, *xk, *xv, *Q, *K, *V, *Q2, *O, *rWq, *rWk, *rWv, *rWo;
    cudaGetSymbolAddress((void**)&xq, g_xq);
    cudaGetSymbolAddress((void**)&xk, g_xk);
    cudaGetSymbolAddress((void**)&xv, g_xv);
    cudaGetSymbolAddress((void**)&Q,  g_Q);
    cudaGetSymbolAddress((void**)&K,  g_K);
    cudaGetSymbolAddress((void**)&V,  g_V);
    cudaGetSymbolAddress((void**)&Q2, g_Q2);
    cudaGetSymbolAddress((void**)&O,  g_O);
    cudaGetSymbolAddress((void**)&rWq, g_Wq);
    cudaGetSymbolAddress((void**)&rWk, g_Wk);
    cudaGetSymbolAddress((void**)&rWv, g_Wv);
    cudaGetSymbolAddress((void**)&rWo, g_Wo);

    static int attr_done = 0;
    if (!attr_done) {
        cudaFuncSetAttribute(attn_mma, cudaFuncAttributeMaxDynamicSharedMemorySize, ATTN_SMEM);
        attr_done = 1;
    }

    int wblk = DD * DD / 4 / 256;   // 1024
    roundw_kernel<<<wblk, 256>>>(Wq, rWq);
    roundw_kernel<<<wblk, 256>>>(Wk, rWk);
    roundw_kernel<<<wblk, 256>>>(Wv, rWv);
    roundw_kernel<<<wblk, 256>>>(Wo, rWo);

    ln3_kernel<<<TOK, 256>>>(data, gk, bk, gq, bq, gv, bv, xq, xk, xv);

    dim3 ggrid(DD / 128, TOK / 128);            // (8, 32)
    gemm_mma<0,1,1><<<ggrid, 256>>>(xq, rWq, bq2, Q);
    gemm_mma<0,1,1><<<ggrid, 256>>>(xk, rWk, bk2, K);
    gemm_mma<0,1,1><<<ggrid, 256>>>(xv, rWv, bv2, V);

    dim3 agrid(SS / 128, BB * HH);              // (16, 32)
    attn_mma<<<agrid, 256, ATTN_SMEM>>>(Q,  K, K, Q2); // Hopfield update
    attn_mma<<<agrid, 256, ATTN_SMEM>>>(Q2, K, V, O);  // retrieval

    gemm_mma<1,0,0><<<ggrid, 256>>>(O, rWo, bo, out);
}

// round 5
// speedup vs baseline: 6.0192x; 1.0827x over previous
#include <cuda_runtime.h>
#include <math.h>

// Problem constants
#define BB   2
#define SS   2048
#define DD   1024
#define HH   16
#define HDIM 64
#define TOK  (BB*SS)           // 4096 rows
#define NSCALE 0.125f          // 1/sqrt(64)
#define LOG2E  1.4426950408889634f

// ---------------------------------------------------------------------------
// Scratch (static __device__ arrays; no allocation allowed)
// ---------------------------------------------------------------------------
__device__ float g_xq[TOK*DD];
__device__ float g_xk[TOK*DD];
__device__ float g_xv[TOK*DD];
__device__ float g_Q [TOK*DD];   // head layout [B,H,S,HD]
__device__ float g_K [TOK*DD];
__device__ float g_V [TOK*DD];
__device__ float g_Kt[TOK*DD];   // transposed [B,H,HD,S]
__device__ float g_Vt[TOK*DD];
__device__ float g_Q2[TOK*DD];
__device__ float g_O [TOK*DD];
__device__ float g_Wq[DD*DD];    // tf32-rounded weights
__device__ float g_Wk[DD*DD];
__device__ float g_Wv[DD*DD];
__device__ float g_Wo[DD*DD];

// ---------------------------------------------------------------------------
// helpers
// ---------------------------------------------------------------------------
__device__ __forceinline__ float tf32r(float x) {
    unsigned u;
    asm("cvt.rna.tf32.f32 %0, %1;" : "=r"(u) : "f"(x));
    return __uint_as_float(u);
}

__device__ __forceinline__ float ex2(float x) {
    float y;
    asm("ex2.approx.ftz.f32 %0, %1;" : "=f"(y) : "f"(x));
    return y;
}

__device__ __forceinline__ void mma8(float* d, const unsigned* a, unsigned b0, unsigned b1) {
    asm volatile(
        "mma.sync.aligned.m16n8k8.row.col.f32.tf32.tf32.f32 "
        "{%0,%1,%2,%3}, {%4,%5,%6,%7}, {%8,%9}, {%0,%1,%2,%3};"
        : "+f"(d[0]), "+f"(d[1]), "+f"(d[2]), "+f"(d[3])
        : "r"(a[0]), "r"(a[1]), "r"(a[2]), "r"(a[3]), "r"(b0), "r"(b1));
}

__device__ __forceinline__ void ldsm4(unsigned& r0, unsigned& r1, unsigned& r2, unsigned& r3,
                                      unsigned addr) {
    asm volatile("ldmatrix.sync.aligned.m8n8.x4.shared.b16 {%0,%1,%2,%3}, [%4];"
        : "=r"(r0), "=r"(r1), "=r"(r2), "=r"(r3) : "r"(addr));
}

__device__ __forceinline__ void cpa16(unsigned dst, const void* src) {
    asm volatile("cp.async.cg.shared.global [%0], [%1], 16;" :: "r"(dst), "l"(src));
}
__device__ __forceinline__ void cpa_commit() { asm volatile("cp.async.commit_group;"); }
__device__ __forceinline__ void cpa_wait0()  { asm volatile("cp.async.wait_group 0;"); }
__device__ __forceinline__ void cpa_wait1()  { asm volatile("cp.async.wait_group 1;"); }

// ---------------------------------------------------------------------------
// Weight pre-round
// ---------------------------------------------------------------------------
__global__ __launch_bounds__(256) void roundw_kernel(
    const float* __restrict__ src, float* __restrict__ dst)
{
    int i = blockIdx.x * 256 + threadIdx.x;
    float4 v = ((const float4*)src)[i];
    ((float4*)dst)[i] = make_float4(tf32r(v.x), tf32r(v.y), tf32r(v.z), tf32r(v.w));
}

// ---------------------------------------------------------------------------
// Per-head transpose: [B,H,S,HD] -> [B,H,HD,S]
// grid (SS/32, HDIM/32, BB*HH), block (32, 8)
// ---------------------------------------------------------------------------
__global__ __launch_bounds__(256) void transpose_kernel(
    const float* __restrict__ src, float* __restrict__ dst)
{
    __shared__ float tile[32][33];
    int bh = blockIdx.z;
    int s0 = blockIdx.x * 32, h0 = blockIdx.y * 32;
    const float* S_ = src + (size_t)bh * SS * HDIM;
    float* D_ = dst + (size_t)bh * SS * HDIM;
    int x = threadIdx.x;
    #pragma unroll
    for (int r = threadIdx.y; r < 32; r += 8)
        tile[r][x] = S_[(size_t)(s0 + r) * HDIM + h0 + x];
    __syncthreads();
    #pragma unroll
    for (int r = threadIdx.y; r < 32; r += 8)
        D_[(size_t)(h0 + r) * SS + s0 + x] = tile[x][r];
}

// ---------------------------------------------------------------------------
// Block reduction (256 threads)
// ---------------------------------------------------------------------------
__device__ __forceinline__ float blk_sum256(float v) {
    __shared__ float red[8];
    int lane = threadIdx.x & 31;
    int w    = threadIdx.x >> 5;
    #pragma unroll
    for (int o = 16; o > 0; o >>= 1) v += __shfl_xor_sync(0xffffffffu, v, o);
    __syncthreads();
    if (lane == 0) red[w] = v;
    __syncthreads();
    return red[0]+red[1]+red[2]+red[3]+red[4]+red[5]+red[6]+red[7];
}

// ---------------------------------------------------------------------------
// Fused triple LayerNorm (outputs tf32-rounded)
// ---------------------------------------------------------------------------
__global__ __launch_bounds__(256) void ln3_kernel(
    const float* __restrict__ data,
    const float* __restrict__ gk, const float* __restrict__ bk,
    const float* __restrict__ gq, const float* __restrict__ bq,
    const float* __restrict__ gv, const float* __restrict__ bv,
    float* __restrict__ xq, float* __restrict__ xk, float* __restrict__ xv)
{
    int row = blockIdx.x;
    int t   = threadIdx.x;
    const float4 x4 = ((const float4*)(data + (size_t)row * DD))[t];
    float s = x4.x + x4.y + x4.z + x4.w;
    float mean = blk_sum256(s) * (1.0f / DD);
    float d0 = x4.x - mean, d1 = x4.y - mean, d2 = x4.z - mean, d3 = x4.w - mean;
    float sq = d0*d0 + d1*d1 + d2*d2 + d3*d3;
    float var = blk_sum256(sq) * (1.0f / DD);
    float r = rsqrtf(var + 1e-5f);
    float n0 = d0*r, n1 = d1*r, n2 = d2*r, n3 = d3*r;

    float4 g4, b4, o4;
    size_t base = (size_t)row * DD;

    g4 = ((const float4*)gq)[t]; b4 = ((const float4*)bq)[t];
    o4 = make_float4(tf32r(n0*g4.x + b4.x), tf32r(n1*g4.y + b4.y),
                     tf32r(n2*g4.z + b4.z), tf32r(n3*g4.w + b4.w));
    ((float4*)(xq + base))[t] = o4;

    g4 = ((const float4*)gk)[t]; b4 = ((const float4*)bk)[t];
    o4 = make_float4(tf32r(n0*g4.x + b4.x), tf32r(n1*g4.y + b4.y),
                     tf32r(n2*g4.z + b4.z), tf32r(n3*g4.w + b4.w));
    ((float4*)(xk + base))[t] = o4;

    g4 = ((const float4*)gv)[t]; b4 = ((const float4*)bv)[t];
    o4 = make_float4(tf32r(n0*g4.x + b4.x), tf32r(n1*g4.y + b4.y),
                     tf32r(n2*g4.z + b4.z), tf32r(n3*g4.w + b4.w));
    ((float4*)(xv + base))[t] = o4;
}

// ---------------------------------------------------------------------------
// tf32 tensor-core GEMM, cp.async double-buffered, BK=32.
// ---------------------------------------------------------------------------
template<int MODE_IN, int MODE_OUT, int ROUND>
__global__ __launch_bounds__(256, 2) void gemm_mma(
    const float* __restrict__ A, const float* __restrict__ W,
    const float* __restrict__ bias, float* __restrict__ C)
{
    constexpr int BM = 128, BN = 128, BK = 32;
    constexpr int APAD = 36;
    constexpr int BPAD = 136;
    constexpr int ASZ = BM * APAD;
    constexpr int BSZ = BK * BPAD;
    __shared__ float As[2 * ASZ];
    __shared__ float Bs[2 * BSZ];

    int tid  = threadIdx.x;
    int lane = tid & 31;
    int w    = tid >> 5;
    int g    = lane >> 2;
    int t    = lane & 3;
    int wm   = (w >> 2) * 64;
    int wn   = (w & 3) * 32;
    int bm   = blockIdx.y * BM;
    int bn   = blockIdx.x * BN;

    int ar = tid >> 1;
    int ac = (tid & 1) * 16;
    int br = tid >> 3;
    int bc = (tid & 7) * 16;

    unsigned as_base = (unsigned)__cvta_generic_to_shared(As);
    unsigned bs_base = (unsigned)__cvta_generic_to_shared(Bs);

    float acc[4][4][4];
    #pragma unroll
    for (int i = 0; i < 4; i++)
        #pragma unroll
        for (int j = 0; j < 4; j++)
            #pragma unroll
            for (int q = 0; q < 4; q++) acc[i][j][q] = 0.f;

    auto load_tile = [&](int it, int stg) {
        int kk = it * BK;
        int gm = bm + ar;
        int gk = kk + ac;
        const float* pa;
        if (MODE_IN == 0) {
            pa = &A[(size_t)gm * DD + gk];
        } else {
            int b  = gm >> 11, s2 = gm & (SS - 1);
            int h  = gk >> 6,  hd = gk & (HDIM - 1);
            pa = &A[(((size_t)(b*HH + h) * SS + s2) * HDIM) + hd];
        }
        unsigned da = as_base + (stg * ASZ + ar * APAD + ac) * 4;
        #pragma unroll
        for (int i = 0; i < 4; i++) cpa16(da + i*16, pa + i*4);
        const float* pb = &W[(size_t)(kk + br) * DD + bn + bc];
        unsigned db = bs_base + (stg * BSZ + br * BPAD + bc) * 4;
        #pragma unroll
        for (int i = 0; i < 4; i++) cpa16(db + i*16, pb + i*4);
    };

    constexpr int KITER = DD / BK;   // 32
    load_tile(0, 0);
    cpa_commit();

    for (int it = 0; it < KITER; it++) {
        int cur = it & 1;
        if (it + 1 < KITER) {
            load_tile(it + 1, cur ^ 1);
            cpa_commit();
            cpa_wait1();
        } else {
            cpa_wait0();
        }
        __syncthreads();

        const float* Ab = As + cur * ASZ;
        const float* Bb = Bs + cur * BSZ;
        #pragma unroll
        for (int ks = 0; ks < 4; ks++) {
            int k0 = ks * 8;
            unsigned af[4][4], bf[4][2];
            #pragma unroll
            for (int mi = 0; mi < 4; mi++) {
                int r = wm + mi * 16 + g;
                af[mi][0] = __float_as_uint(Ab[(r    ) * APAD + k0 + t    ]);
                af[mi][1] = __float_as_uint(Ab[(r + 8) * APAD + k0 + t    ]);
                af[mi][2] = __float_as_uint(Ab[(r    ) * APAD + k0 + t + 4]);
                af[mi][3] = __float_as_uint(Ab[(r + 8) * APAD + k0 + t + 4]);
            }
            #pragma unroll
            for (int ni = 0; ni < 4; ni++) {
                int c = wn + ni * 8 + g;
                bf[ni][0] = __float_as_uint(Bb[(k0 + t    ) * BPAD + c]);
                bf[ni][1] = __float_as_uint(Bb[(k0 + t + 4) * BPAD + c]);
            }
            #pragma unroll
            for (int mi = 0; mi < 4; mi++)
                #pragma unroll
                for (int ni = 0; ni < 4; ni++)
                    mma8(acc[mi][ni], af[mi], bf[ni][0], bf[ni][1]);
        }
        __syncthreads();
    }

    #pragma unroll
    for (int mi = 0; mi < 4; mi++) {
        #pragma unroll
        for (int ni = 0; ni < 4; ni++) {
            int row = bm + wm + mi * 16 + g;
            int col = bn + wn + ni * 8 + 2 * t;
            float2 bia = *(const float2*)&bias[col];
            float2 v0, v1;
            if (ROUND) {
                v0 = make_float2(tf32r(acc[mi][ni][0] + bia.x), tf32r(acc[mi][ni][1] + bia.y));
                v1 = make_float2(tf32r(acc[mi][ni][2] + bia.x), tf32r(acc[mi][ni][3] + bia.y));
            } else {
                v0 = make_float2(acc[mi][ni][0] + bia.x, acc[mi][ni][1] + bia.y);
                v1 = make_float2(acc[mi][ni][2] + bia.x, acc[mi][ni][3] + bia.y);
            }
            if (MODE_OUT == 0) {
                *(float2*)&C[(size_t)row * DD + col]       = v0;
                *(float2*)&C[(size_t)(row + 8) * DD + col] = v1;
            } else {
                int h = col >> 6, hd = col & (HDIM - 1);
                int b0i = row >> 11,       s0 = row & (SS - 1);
                int b1i = (row + 8) >> 11, s1 = (row + 8) & (SS - 1);
                *(float2*)&C[((size_t)(b0i*HH + h) * SS + s0) * HDIM + hd] = v0;
                *(float2*)&C[((size_t)(b1i*HH + h) * SS + s1) * HDIM + hd] = v1;
            }
        }
    }
}

// ---------------------------------------------------------------------------
// Flash attention, tf32 mma with ldmatrix fragments, no-max softmax (base-2).
// Out = softmax(NSCALE * Qin Kin^T) @ V,  V given TRANSPOSED: Vtin [B,H,HD,S].
// 256 threads = 8 warps; CTA = 128 queries (16/warp); K-tile 64 keys.
// Dyn smem: K[2][64][68] (key x hd) | T[2][64][68] (hd x key) | P[8][16][68]
// ---------------------------------------------------------------------------
#define TSP 68
#define PSP 68
#define TILESZ (64*TSP)
#define ATTN_SMEM ((4*TILESZ + 8*16*PSP) * 4)

__global__ __launch_bounds__(256, 2) void attn_mma(
    const float* __restrict__ Qin, const float* __restrict__ Kin,
    const float* __restrict__ Vtin, float* __restrict__ Out)
{
    extern __shared__ float sm[];
    float* Ks = sm;                 // [2][64][TSP]  keys x hd
    float* Ts = sm + 2 * TILESZ;    // [2][64][TSP]  hd x keys (V^T tile)
    float* Ps = sm + 4 * TILESZ;    // [8][16][PSP]
    unsigned ks_base = (unsigned)__cvta_generic_to_shared(Ks);
    unsigned ts_base = (unsigned)__cvta_generic_to_shared(Ts);
    unsigned ps_base = (unsigned)__cvta_generic_to_shared(Ps);

    int tid  = threadIdx.x;
    int lane = tid & 31;
    int w    = tid >> 5;
    int g    = lane >> 2;
    int t    = lane & 3;
    int bh   = blockIdx.y;
    int q0   = blockIdx.x * 128;
    size_t base = (size_t)bh * SS * HDIM;   // same element count for both layouts

    // Q fragments scaled by beta*log2(e): softmax(beta*s) == 2^(s') normalization
    const float QS = NSCALE * LOG2E;
    unsigned qa[8][4];
    {
        const float* Qp = Qin + base;
        int r0 = q0 + w * 16 + g;
        #pragma unroll
        for (int ks = 0; ks < 8; ks++) {
            qa[ks][0] = __float_as_uint(tf32r(Qp[(size_t)r0     * HDIM + ks*8 + t    ] * QS));
            qa[ks][1] = __float_as_uint(tf32r(Qp[(size_t)(r0+8) * HDIM + ks*8 + t    ] * QS));
            qa[ks][2] = __float_as_uint(tf32r(Qp[(size_t)r0     * HDIM + ks*8 + t + 4] * QS));
            qa[ks][3] = __float_as_uint(tf32r(Qp[(size_t)(r0+8) * HDIM + ks*8 + t + 4] * QS));
        }
    }

    float o[8][4];
    #pragma unroll
    for (int j = 0; j < 8; j++)
        #pragma unroll
        for (int q = 0; q < 4; q++) o[j][q] = 0.f;
    float l0 = 0.f, l1 = 0.f;

    // cooperative loader: 256 threads, two 64x64 tiles, 16 floats/thread each
    int lrow = tid >> 2;          // 0..63
    int lcol = (tid & 3) * 16;    // 0,16,32,48

    auto load_kv = [&](int kt, int stg) {
        const float* Kp = Kin  + base + (size_t)(kt*64 + lrow) * HDIM + lcol;   // key-row
        const float* Tp = Vtin + base + (size_t)lrow * SS + kt*64 + lcol;        // hd-row
        unsigned kd = ks_base + (stg * TILESZ + lrow * TSP + lcol) * 4;
        unsigned td = ts_base + (stg * TILESZ + lrow * TSP + lcol) * 4;
        #pragma unroll
        for (int i = 0; i < 4; i++) cpa16(kd + i*16, Kp + i*4);
        #pragma unroll
        for (int i = 0; i < 4; i++) cpa16(td + i*16, Tp + i*4);
    };

    // ldmatrix per-thread base addresses (lane -> matrix row / chunk)
    unsigned kfrag = ks_base + (((lane & 7) * TSP + (lane >> 3) * 4) * 4);
    unsigned tfrag = ts_base + (((lane & 7) * TSP + (lane >> 3) * 4) * 4);
    float*   Pwp   = Ps + w * 16 * PSP;
    unsigned pfrag = ps_base + ((w * 16 * PSP +
                     (((lane >> 3) & 1) * 8 + (lane & 7)) * PSP + (lane >> 4) * 4) * 4);

    constexpr int NT = SS / 64;   // 32
    load_kv(0, 0);
    cpa_commit();

    for (int kt = 0; kt < NT; kt++) {
        int cur = kt & 1;
        if (kt + 1 < NT) {
            load_kv(kt + 1, cur ^ 1);
            cpa_commit();
            cpa_wait1();
        } else {
            cpa_wait0();
        }
        __syncthreads();

        unsigned kf = kfrag + cur * TILESZ * 4;
        unsigned tf = tfrag + cur * TILESZ * 4;

        // ---- S = Q K^T, p = 2^S, store P ----
        #pragma unroll
        for (int n = 0; n < 8; n++) {
            float sa[4] = {0.f, 0.f, 0.f, 0.f};
            #pragma unroll
            for (int cp = 0; cp < 4; cp++) {
                unsigned b0, b1, b2, b3;
                ldsm4(b0, b1, b2, b3, kf + (n*8*TSP + cp*16) * 4);
                mma8(sa, qa[2*cp    ], b0, b1);
                mma8(sa, qa[2*cp + 1], b2, b3);
            }
            float p0 = ex2(sa[0]), p1 = ex2(sa[1]);
            float p2 = ex2(sa[2]), p3 = ex2(sa[3]);
            l0 += p0 + p1;
            l1 += p2 + p3;
            *(float2*)(Pwp +  g      * PSP + n*8 + 2*t) = make_float2(tf32r(p0), tf32r(p1));
            *(float2*)(Pwp + (g + 8) * PSP + n*8 + 2*t) = make_float2(tf32r(p2), tf32r(p3));
        }
        __syncwarp();

        // ---- O += P V : a-fragments from P, b-fragments from V^T tile ----
        unsigned pa[8][4];
        #pragma unroll
        for (int ks = 0; ks < 8; ks++)
            ldsm4(pa[ks][0], pa[ks][1], pa[ks][2], pa[ks][3], pfrag + ks*32);

        #pragma unroll
        for (int j = 0; j < 8; j++) {
            #pragma unroll
            for (int cp = 0; cp < 4; cp++) {
                unsigned v0, v1, v2, v3;
                ldsm4(v0, v1, v2, v3, tf + (j*8*TSP + cp*16) * 4);
                mma8(o[j], pa[2*cp    ], v0, v1);
                mma8(o[j], pa[2*cp + 1], v2, v3);
            }
        }
        __syncthreads();
    }

    // final row-sum reduction over the 4 t-lanes
    l0 += __shfl_xor_sync(0xffffffffu, l0, 1);
    l0 += __shfl_xor_sync(0xffffffffu, l0, 2);
    l1 += __shfl_xor_sync(0xffffffffu, l1, 1);
    l1 += __shfl_xor_sync(0xffffffffu, l1, 2);
    float inv0 = 1.f / l0, inv1 = 1.f / l1;

    int r0 = q0 + w * 16 + g;
    float* Op = Out + base;
    #pragma unroll
    for (int j = 0; j < 8; j++) {
        *(float2*)&Op[(size_t)r0     * HDIM + j*8 + 2*t] =
            make_float2(tf32r(o[j][0] * inv0), tf32r(o[j][1] * inv0));
        *(float2*)&Op[(size_t)(r0+8) * HDIM + j*8 + 2*t] =
            make_float2(tf32r(o[j][2] * inv1), tf32r(o[j][3] * inv1));
    }
}

// ---------------------------------------------------------------------------
// Launch
// ---------------------------------------------------------------------------
extern "C" void kernel_launch(void* const* d_in, const int* in_sizes, int n_in,
                              void* d_out, int out_size)
{
    const float* data = (const float*)d_in[0];
    const float* gk   = (const float*)d_in[1];
    const float* bk   = (const float*)d_in[2];
    const float* gq   = (const float*)d_in[3];
    const float* bq   = (const float*)d_in[4];
    const float* gv   = (const float*)d_in[5];
    const float* bv   = (const float*)d_in[6];
    const float* Wq   = (const float*)d_in[7];
    const float* bq2  = (const float*)d_in[8];
    const float* Wk   = (const float*)d_in[9];
    const float* bk2  = (const float*)d_in[10];
    const float* Wv   = (const float*)d_in[11];
    const float* bv2  = (const float*)d_in[12];
    const float* Wo   = (const float*)d_in[13];
    const float* bo   = (const float*)d_in[14];
    float* out = (float*)d_out;

    float *xq, *xk, *xv, *Q, *K, *V, *Kt, *Vt, *Q2, *O, *rWq, *rWk, *rWv, *rWo;
    cudaGetSymbolAddress((void**)&xq, g_xq);
    cudaGetSymbolAddress((void**)&xk, g_xk);
    cudaGetSymbolAddress((void**)&xv, g_xv);
    cudaGetSymbolAddress((void**)&Q,  g_Q);
    cudaGetSymbolAddress((void**)&K,  g_K);
    cudaGetSymbolAddress((void**)&V,  g_V);
    cudaGetSymbolAddress((void**)&Kt, g_Kt);
    cudaGetSymbolAddress((void**)&Vt, g_Vt);
    cudaGetSymbolAddress((void**)&Q2, g_Q2);
    cudaGetSymbolAddress((void**)&O,  g_O);
    cudaGetSymbolAddress((void**)&rWq, g_Wq);
    cudaGetSymbolAddress((void**)&rWk, g_Wk);
    cudaGetSymbolAddress((void**)&rWv, g_Wv);
    cudaGetSymbolAddress((void**)&rWo, g_Wo);

    static int attr_done = 0;
    if (!attr_done) {
        cudaFuncSetAttribute(attn_mma, cudaFuncAttributeMaxDynamicSharedMemorySize, ATTN_SMEM);
        attr_done = 1;
    }

    int wblk = DD * DD / 4 / 256;   // 1024
    roundw_kernel<<<wblk, 256>>>(Wq, rWq);
    roundw_kernel<<<wblk, 256>>>(Wk, rWk);
    roundw_kernel<<<wblk, 256>>>(Wv, rWv);
    roundw_kernel<<<wblk, 256>>>(Wo, rWo);

    ln3_kernel<<<TOK, 256>>>(data, gk, bk, gq, bq, gv, bv, xq, xk, xv);

    dim3 ggrid(DD / 128, TOK / 128);            // (8, 32)
    gemm_mma<0,1,1><<<ggrid, 256>>>(xq, rWq, bq2, Q);
    gemm_mma<0,1,1><<<ggrid, 256>>>(xk, rWk, bk2, K);
    gemm_mma<0,1,1><<<ggrid, 256>>>(xv, rWv, bv2, V);

    dim3 tgrid(SS / 32, HDIM / 32, BB * HH);
    dim3 tblk(32, 8);
    transpose_kernel<<<tgrid, tblk>>>(K, Kt);
    transpose_kernel<<<tgrid, tblk>>>(V, Vt);

    dim3 agrid(SS / 128, BB * HH);              // (16, 32)
    attn_mma<<<agrid, 256, ATTN_SMEM>>>(Q,  K, Kt, Q2); // Hopfield update: V = K
    attn_mma<<<agrid, 256, ATTN_SMEM>>>(Q2, K, Vt, O);  // retrieval

    gemm_mma<1,0,0><<<ggrid, 256>>>(O, rWo, bo, out);
}

// round 6
// speedup vs baseline: 6.1682x; 1.0248x over previous
#include <cuda_runtime.h>
#include <math.h>

// Problem constants
#define BB   2
#define SS   2048
#define DD   1024
#define HH   16
#define HDIM 64
#define TOK  (BB*SS)           // 4096 rows
#define NSCALE 0.125f          // 1/sqrt(64)
#define LOG2E  1.4426950408889634f

// ---------------------------------------------------------------------------
// Scratch (static __device__ arrays; no allocation allowed)
// ---------------------------------------------------------------------------
__device__ float g_xq[TOK*DD];
__device__ float g_xk[TOK*DD];
__device__ float g_xv[TOK*DD];
__device__ float g_Q [TOK*DD];   // head layout [B,H,S,HD]
__device__ float g_K [TOK*DD];
__device__ float g_V [TOK*DD];
__device__ float g_Kt[TOK*DD];   // transposed [B,H,HD,S]
__device__ float g_Vt[TOK*DD];
__device__ float g_O [TOK*DD];
__device__ float g_Wq[DD*DD];    // tf32-rounded weights
__device__ float g_Wk[DD*DD];
__device__ float g_Wv[DD*DD];
__device__ float g_Wo[DD*DD];

// ---------------------------------------------------------------------------
// helpers
// ---------------------------------------------------------------------------
__device__ __forceinline__ float tf32r(float x) {
    unsigned u;
    asm("cvt.rna.tf32.f32 %0, %1;" : "=r"(u) : "f"(x));
    return __uint_as_float(u);
}

__device__ __forceinline__ float ex2(float x) {
    float y;
    asm("ex2.approx.ftz.f32 %0, %1;" : "=f"(y) : "f"(x));
    return y;
}

__device__ __forceinline__ void mma8(float* d, const unsigned* a, unsigned b0, unsigned b1) {
    asm volatile(
        "mma.sync.aligned.m16n8k8.row.col.f32.tf32.tf32.f32 "
        "{%0,%1,%2,%3}, {%4,%5,%6,%7}, {%8,%9}, {%0,%1,%2,%3};"
        : "+f"(d[0]), "+f"(d[1]), "+f"(d[2]), "+f"(d[3])
        : "r"(a[0]), "r"(a[1]), "r"(a[2]), "r"(a[3]), "r"(b0), "r"(b1));
}

__device__ __forceinline__ void ldsm4(unsigned& r0, unsigned& r1, unsigned& r2, unsigned& r3,
                                      unsigned addr) {
    asm volatile("ldmatrix.sync.aligned.m8n8.x4.shared.b16 {%0,%1,%2,%3}, [%4];"
        : "=r"(r0), "=r"(r1), "=r"(r2), "=r"(r3) : "r"(addr));
}

__device__ __forceinline__ void cpa16(unsigned dst, const void* src) {
    asm volatile("cp.async.cg.shared.global [%0], [%1], 16;" :: "r"(dst), "l"(src));
}
__device__ __forceinline__ void cpa_commit() { asm volatile("cp.async.commit_group;"); }
__device__ __forceinline__ void cpa_wait0()  { asm volatile("cp.async.wait_group 0;"); }
__device__ __forceinline__ void cpa_wait1()  { asm volatile("cp.async.wait_group 1;"); }

// ---------------------------------------------------------------------------
// Weight pre-round, all 4 weights in one launch: grid (1024, 4)
// ---------------------------------------------------------------------------
__global__ __launch_bounds__(256) void roundw_all(
    const float* __restrict__ w0, const float* __restrict__ w1,
    const float* __restrict__ w2, const float* __restrict__ w3,
    float* __restrict__ d0, float* __restrict__ d1,
    float* __restrict__ d2, float* __restrict__ d3)
{
    const float* src; float* dst;
    switch (blockIdx.y) {
        case 0: src = w0; dst = d0; break;
        case 1: src = w1; dst = d1; break;
        case 2: src = w2; dst = d2; break;
        default: src = w3; dst = d3; break;
    }
    int i = blockIdx.x * 256 + threadIdx.x;
    float4 v = ((const float4*)src)[i];
    ((float4*)dst)[i] = make_float4(tf32r(v.x), tf32r(v.y), tf32r(v.z), tf32r(v.w));
}

// ---------------------------------------------------------------------------
// Per-head transpose: [B,H,S,HD] -> [B,H,HD,S]; two tensors in one launch.
// grid (SS/32, HDIM/32, 2*BB*HH), block (32, 8)
// ---------------------------------------------------------------------------
__global__ __launch_bounds__(256) void transpose_both(
    const float* __restrict__ srcA, float* __restrict__ dstA,
    const float* __restrict__ srcB, float* __restrict__ dstB)
{
    __shared__ float tile[32][33];
    int z  = blockIdx.z;
    int bh = z & (BB*HH - 1);
    const float* src = (z < BB*HH) ? srcA : srcB;
    float*       dst = (z < BB*HH) ? dstA : dstB;
    int s0 = blockIdx.x * 32, h0 = blockIdx.y * 32;
    const float* S_ = src + (size_t)bh * SS * HDIM;
    float* D_ = dst + (size_t)bh * SS * HDIM;
    int x = threadIdx.x;
    #pragma unroll
    for (int r = threadIdx.y; r < 32; r += 8)
        tile[r][x] = S_[(size_t)(s0 + r) * HDIM + h0 + x];
    __syncthreads();
    #pragma unroll
    for (int r = threadIdx.y; r < 32; r += 8)
        D_[(size_t)(h0 + r) * SS + s0 + x] = tile[x][r];
}

// ---------------------------------------------------------------------------
// Block reduction (256 threads)
// ---------------------------------------------------------------------------
__device__ __forceinline__ float blk_sum256(float v) {
    __shared__ float red[8];
    int lane = threadIdx.x & 31;
    int w    = threadIdx.x >> 5;
    #pragma unroll
    for (int o = 16; o > 0; o >>= 1) v += __shfl_xor_sync(0xffffffffu, v, o);
    __syncthreads();
    if (lane == 0) red[w] = v;
    __syncthreads();
    return red[0]+red[1]+red[2]+red[3]+red[4]+red[5]+red[6]+red[7];
}

// ---------------------------------------------------------------------------
// Fused triple LayerNorm (outputs tf32-rounded)
// ---------------------------------------------------------------------------
__global__ __launch_bounds__(256) void ln3_kernel(
    const float* __restrict__ data,
    const float* __restrict__ gk, const float* __restrict__ bk,
    const float* __restrict__ gq, const float* __restrict__ bq,
    const float* __restrict__ gv, const float* __restrict__ bv,
    float* __restrict__ xq, float* __restrict__ xk, float* __restrict__ xv)
{
    int row = blockIdx.x;
    int t   = threadIdx.x;
    const float4 x4 = ((const float4*)(data + (size_t)row * DD))[t];
    float s = x4.x + x4.y + x4.z + x4.w;
    float mean = blk_sum256(s) * (1.0f / DD);
    float d0 = x4.x - mean, d1 = x4.y - mean, d2 = x4.z - mean, d3 = x4.w - mean;
    float sq = d0*d0 + d1*d1 + d2*d2 + d3*d3;
    float var = blk_sum256(sq) * (1.0f / DD);
    float r = rsqrtf(var + 1e-5f);
    float n0 = d0*r, n1 = d1*r, n2 = d2*r, n3 = d3*r;

    float4 g4, b4, o4;
    size_t base = (size_t)row * DD;

    g4 = ((const float4*)gq)[t]; b4 = ((const float4*)bq)[t];
    o4 = make_float4(tf32r(n0*g4.x + b4.x), tf32r(n1*g4.y + b4.y),
                     tf32r(n2*g4.z + b4.z), tf32r(n3*g4.w + b4.w));
    ((float4*)(xq + base))[t] = o4;

    g4 = ((const float4*)gk)[t]; b4 = ((const float4*)bk)[t];
    o4 = make_float4(tf32r(n0*g4.x + b4.x), tf32r(n1*g4.y + b4.y),
                     tf32r(n2*g4.z + b4.z), tf32r(n3*g4.w + b4.w));
    ((float4*)(xk + base))[t] = o4;

    g4 = ((const float4*)gv)[t]; b4 = ((const float4*)bv)[t];
    o4 = make_float4(tf32r(n0*g4.x + b4.x), tf32r(n1*g4.y + b4.y),
                     tf32r(n2*g4.z + b4.z), tf32r(n3*g4.w + b4.w));
    ((float4*)(xv + base))[t] = o4;
}

// ---------------------------------------------------------------------------
// tf32 tensor-core GEMM body (device inline), cp.async double-buffered, BK=32.
// ---------------------------------------------------------------------------
template<int MODE_IN, int MODE_OUT, int ROUND>
__device__ __forceinline__ void gemm_body(
    const float* __restrict__ A, const float* __restrict__ W,
    const float* __restrict__ bias, float* __restrict__ C)
{
    constexpr int BM = 128, BN = 128, BK = 32;
    constexpr int APAD = 36;
    constexpr int BPAD = 136;
    constexpr int ASZ = BM * APAD;
    constexpr int BSZ = BK * BPAD;
    __shared__ float As[2 * ASZ];
    __shared__ float Bs[2 * BSZ];

    int tid  = threadIdx.x;
    int lane = tid & 31;
    int w    = tid >> 5;
    int g    = lane >> 2;
    int t    = lane & 3;
    int wm   = (w >> 2) * 64;
    int wn   = (w & 3) * 32;
    int bm   = blockIdx.y * BM;
    int bn   = blockIdx.x * BN;

    int ar = tid >> 1;
    int ac = (tid & 1) * 16;
    int br = tid >> 3;
    int bc = (tid & 7) * 16;

    unsigned as_base = (unsigned)__cvta_generic_to_shared(As);
    unsigned bs_base = (unsigned)__cvta_generic_to_shared(Bs);

    float acc[4][4][4];
    #pragma unroll
    for (int i = 0; i < 4; i++)
        #pragma unroll
        for (int j = 0; j < 4; j++)
            #pragma unroll
            for (int q = 0; q < 4; q++) acc[i][j][q] = 0.f;

    auto load_tile = [&](int it, int stg) {
        int kk = it * BK;
        int gm = bm + ar;
        int gk = kk + ac;
        const float* pa;
        if (MODE_IN == 0) {
            pa = &A[(size_t)gm * DD + gk];
        } else {
            int b  = gm >> 11, s2 = gm & (SS - 1);
            int h  = gk >> 6,  hd = gk & (HDIM - 1);
            pa = &A[(((size_t)(b*HH + h) * SS + s2) * HDIM) + hd];
        }
        unsigned da = as_base + (stg * ASZ + ar * APAD + ac) * 4;
        #pragma unroll
        for (int i = 0; i < 4; i++) cpa16(da + i*16, pa + i*4);
        const float* pb = &W[(size_t)(kk + br) * DD + bn + bc];
        unsigned db = bs_base + (stg * BSZ + br * BPAD + bc) * 4;
        #pragma unroll
        for (int i = 0; i < 4; i++) cpa16(db + i*16, pb + i*4);
    };

    constexpr int KITER = DD / BK;   // 32
    load_tile(0, 0);
    cpa_commit();

    for (int it = 0; it < KITER; it++) {
        int cur = it & 1;
        if (it + 1 < KITER) {
            load_tile(it + 1, cur ^ 1);
            cpa_commit();
            cpa_wait1();
        } else {
            cpa_wait0();
        }
        __syncthreads();

        const float* Ab = As + cur * ASZ;
        const float* Bb = Bs + cur * BSZ;
        #pragma unroll
        for (int ks = 0; ks < 4; ks++) {
            int k0 = ks * 8;
            unsigned af[4][4], bf[4][2];
            #pragma unroll
            for (int mi = 0; mi < 4; mi++) {
                int r = wm + mi * 16 + g;
                af[mi][0] = __float_as_uint(Ab[(r    ) * APAD + k0 + t    ]);
                af[mi][1] = __float_as_uint(Ab[(r + 8) * APAD + k0 + t    ]);
                af[mi][2] = __float_as_uint(Ab[(r    ) * APAD + k0 + t + 4]);
                af[mi][3] = __float_as_uint(Ab[(r + 8) * APAD + k0 + t + 4]);
            }
            #pragma unroll
            for (int ni = 0; ni < 4; ni++) {
                int c = wn + ni * 8 + g;
                bf[ni][0] = __float_as_uint(Bb[(k0 + t    ) * BPAD + c]);
                bf[ni][1] = __float_as_uint(Bb[(k0 + t + 4) * BPAD + c]);
            }
            #pragma unroll
            for (int mi = 0; mi < 4; mi++)
                #pragma unroll
                for (int ni = 0; ni < 4; ni++)
                    mma8(acc[mi][ni], af[mi], bf[ni][0], bf[ni][1]);
        }
        __syncthreads();
    }

    #pragma unroll
    for (int mi = 0; mi < 4; mi++) {
        #pragma unroll
        for (int ni = 0; ni < 4; ni++) {
            int row = bm + wm + mi * 16 + g;
            int col = bn + wn + ni * 8 + 2 * t;
            float2 bia = *(const float2*)&bias[col];
            float2 v0, v1;
            if (ROUND) {
                v0 = make_float2(tf32r(acc[mi][ni][0] + bia.x), tf32r(acc[mi][ni][1] + bia.y));
                v1 = make_float2(tf32r(acc[mi][ni][2] + bia.x), tf32r(acc[mi][ni][3] + bia.y));
            } else {
                v0 = make_float2(acc[mi][ni][0] + bia.x, acc[mi][ni][1] + bia.y);
                v1 = make_float2(acc[mi][ni][2] + bia.x, acc[mi][ni][3] + bia.y);
            }
            if (MODE_OUT == 0) {
                *(float2*)&C[(size_t)row * DD + col]       = v0;
                *(float2*)&C[(size_t)(row + 8) * DD + col] = v1;
            } else {
                int h = col >> 6, hd = col & (HDIM - 1);
                int b0i = row >> 11,       s0 = row & (SS - 1);
                int b1i = (row + 8) >> 11, s1 = (row + 8) & (SS - 1);
                *(float2*)&C[((size_t)(b0i*HH + h) * SS + s0) * HDIM + hd] = v0;
                *(float2*)&C[((size_t)(b1i*HH + h) * SS + s1) * HDIM + hd] = v1;
            }
        }
    }
}

// Batched Q/K/V projection: grid (8, 32, 3)
__global__ __launch_bounds__(256, 2) void gemm_qkv(
    const float* __restrict__ xq, const float* __restrict__ xk, const float* __restrict__ xv,
    const float* __restrict__ Wq, const float* __restrict__ Wk, const float* __restrict__ Wv,
    const float* __restrict__ bq, const float* __restrict__ bk, const float* __restrict__ bv,
    float* __restrict__ Q, float* __restrict__ K, float* __restrict__ V)
{
    const float* A; const float* W; const float* bias; float* C;
    if (blockIdx.z == 0)      { A = xq; W = Wq; bias = bq; C = Q; }
    else if (blockIdx.z == 1) { A = xk; W = Wk; bias = bk; C = K; }
    else                      { A = xv; W = Wv; bias = bv; C = V; }
    gemm_body<0, 1, 1>(A, W, bias, C);
}

// Output projection: grid (8, 32)
__global__ __launch_bounds__(256, 2) void gemm_out(
    const float* __restrict__ A, const float* __restrict__ W,
    const float* __restrict__ bias, float* __restrict__ C)
{
    gemm_body<1, 0, 0>(A, W, bias, C);
}

// ---------------------------------------------------------------------------
// FUSED double-pass flash attention (Hopfield update + retrieval).
//   pass 1: Q2 = softmax(b Q K^T) K      (V^T tile source = Kt)
//   pass 2: O  = softmax(b Q2 K^T) V     (V^T tile source = Vt)
// 256 threads = 8 warps; CTA = 128 queries (16/warp); K-tile 64 keys.
// Dyn smem: K[2][64][68] | T[2][64][68] | P[8][16][68]
// ---------------------------------------------------------------------------
#define TSP 68
#define PSP 68
#define TILESZ (64*TSP)
#define ATTN_SMEM ((4*TILESZ + 8*16*PSP) * 4)

__global__ __launch_bounds__(256, 2) void attn_fused(
    const float* __restrict__ Qin, const float* __restrict__ Kin,
    const float* __restrict__ Ktin, const float* __restrict__ Vtin,
    float* __restrict__ Out)
{
    extern __shared__ float sm[];
    float* Ks = sm;                 // [2][64][TSP]  keys x hd
    float* Ts = sm + 2 * TILESZ;    // [2][64][TSP]  hd x keys (V^T tile)
    float* Ps = sm + 4 * TILESZ;    // [8][16][PSP]
    unsigned ks_base = (unsigned)__cvta_generic_to_shared(Ks);
    unsigned ts_base = (unsigned)__cvta_generic_to_shared(Ts);
    unsigned ps_base = (unsigned)__cvta_generic_to_shared(Ps);

    int tid  = threadIdx.x;
    int lane = tid & 31;
    int w    = tid >> 5;
    int g    = lane >> 2;
    int t    = lane & 3;
    int bh   = blockIdx.y;
    int q0   = blockIdx.x * 128;
    size_t base = (size_t)bh * SS * HDIM;

    const float QS = NSCALE * LOG2E;

    // cooperative loader mapping
    int lrow = tid >> 2;          // 0..63
    int lcol = (tid & 3) * 16;    // 0,16,32,48

    // ldmatrix per-thread base addresses
    unsigned kfrag = ks_base + (((lane & 7) * TSP + (lane >> 3) * 4) * 4);
    unsigned tfrag = ts_base + (((lane & 7) * TSP + (lane >> 3) * 4) * 4);
    float*   Pwp   = Ps + w * 16 * PSP;
    unsigned pfrag = ps_base + ((w * 16 * PSP +
                     (((lane >> 3) & 1) * 8 + (lane & 7)) * PSP + (lane >> 4) * 4) * 4);

    // ---- Q fragments for pass 1 (global, pre-scaled) ----
    unsigned qa[8][4];
    {
        const float* Qp = Qin + base;
        int r0 = q0 + w * 16 + g;
        #pragma unroll
        for (int ks = 0; ks < 8; ks++) {
            qa[ks][0] = __float_as_uint(tf32r(Qp[(size_t)r0     * HDIM + ks*8 + t    ] * QS));
            qa[ks][1] = __float_as_uint(tf32r(Qp[(size_t)(r0+8) * HDIM + ks*8 + t    ] * QS));
            qa[ks][2] = __float_as_uint(tf32r(Qp[(size_t)r0     * HDIM + ks*8 + t + 4] * QS));
            qa[ks][3] = __float_as_uint(tf32r(Qp[(size_t)(r0+8) * HDIM + ks*8 + t + 4] * QS));
        }
    }

    float o[8][4];
    float l0, l1;
    constexpr int NT = SS / 64;   // 32

    // ---- one flash pass over all K tiles; Tsrc = transposed V source ----
    auto flash_pass = [&](const float* __restrict__ Tsrc) {
        #pragma unroll
        for (int j = 0; j < 8; j++)
            #pragma unroll
            for (int q = 0; q < 4; q++) o[j][q] = 0.f;
        l0 = 0.f; l1 = 0.f;

        auto load_kv = [&](int kt, int stg) {
            const float* Kp = Kin  + base + (size_t)(kt*64 + lrow) * HDIM + lcol;
            const float* Tp = Tsrc + base + (size_t)lrow * SS + kt*64 + lcol;
            unsigned kd = ks_base + (stg * TILESZ + lrow * TSP + lcol) * 4;
            unsigned td = ts_base + (stg * TILESZ + lrow * TSP + lcol) * 4;
            #pragma unroll
            for (int i = 0; i < 4; i++) cpa16(kd + i*16, Kp + i*4);
            #pragma unroll
            for (int i = 0; i < 4; i++) cpa16(td + i*16, Tp + i*4);
        };

        load_kv(0, 0);
        cpa_commit();

        for (int kt = 0; kt < NT; kt++) {
            int cur = kt & 1;
            if (kt + 1 < NT) {
                load_kv(kt + 1, cur ^ 1);
                cpa_commit();
                cpa_wait1();
            } else {
                cpa_wait0();
            }
            __syncthreads();

            unsigned kf = kfrag + cur * TILESZ * 4;
            unsigned tf = tfrag + cur * TILESZ * 4;

            // S = Q K^T, p = 2^S, store P
            #pragma unroll
            for (int n = 0; n < 8; n++) {
                float sa[4] = {0.f, 0.f, 0.f, 0.f};
                #pragma unroll
                for (int cp = 0; cp < 4; cp++) {
                    unsigned b0, b1, b2, b3;
                    ldsm4(b0, b1, b2, b3, kf + (n*8*TSP + cp*16) * 4);
                    mma8(sa, qa[2*cp    ], b0, b1);
                    mma8(sa, qa[2*cp + 1], b2, b3);
                }
                float p0 = ex2(sa[0]), p1 = ex2(sa[1]);
                float p2 = ex2(sa[2]), p3 = ex2(sa[3]);
                l0 += p0 + p1;
                l1 += p2 + p3;
                *(float2*)(Pwp +  g      * PSP + n*8 + 2*t) = make_float2(tf32r(p0), tf32r(p1));
                *(float2*)(Pwp + (g + 8) * PSP + n*8 + 2*t) = make_float2(tf32r(p2), tf32r(p3));
            }
            __syncwarp();

            // O += P V
            unsigned pa[8][4];
            #pragma unroll
            for (int ks = 0; ks < 8; ks++)
                ldsm4(pa[ks][0], pa[ks][1], pa[ks][2], pa[ks][3], pfrag + ks*32);

            #pragma unroll
            for (int j = 0; j < 8; j++) {
                #pragma unroll
                for (int cp = 0; cp < 4; cp++) {
                    unsigned v0, v1, v2, v3;
                    ldsm4(v0, v1, v2, v3, tf + (j*8*TSP + cp*16) * 4);
                    mma8(o[j], pa[2*cp    ], v0, v1);
                    mma8(o[j], pa[2*cp + 1], v2, v3);
                }
            }
            __syncthreads();
        }

        // row-sum over 4 t-lanes
        l0 += __shfl_xor_sync(0xffffffffu, l0, 1);
        l0 += __shfl_xor_sync(0xffffffffu, l0, 2);
        l1 += __shfl_xor_sync(0xffffffffu, l1, 1);
        l1 += __shfl_xor_sync(0xffffffffu, l1, 2);
    };

    // ================= PASS 1: Hopfield update (V = K) =================
    flash_pass(Ktin);

    // Q2 = O/l, rescaled by QS; round, store to P region, reload as a-frags.
    {
        float s0 = QS / l0, s1 = QS / l1;
        #pragma unroll
        for (int j = 0; j < 8; j++) {
            *(float2*)(Pwp +  g      * PSP + j*8 + 2*t) =
                make_float2(tf32r(o[j][0] * s0), tf32r(o[j][1] * s0));
            *(float2*)(Pwp + (g + 8) * PSP + j*8 + 2*t) =
                make_float2(tf32r(o[j][2] * s1), tf32r(o[j][3] * s1));
        }
        __syncwarp();
        #pragma unroll
        for (int ks = 0; ks < 8; ks++)
            ldsm4(qa[ks][0], qa[ks][1], qa[ks][2], qa[ks][3], pfrag + ks*32);
    }
    __syncthreads();   // all warps done with smem before pass-2 preload

    // ================= PASS 2: retrieval (V = V) =================
    flash_pass(Vtin);

    // ---- epilogue ----
    float inv0 = 1.f / l0, inv1 = 1.f / l1;
    int r0 = q0 + w * 16 + g;
    float* Op = Out + base;
    #pragma unroll
    for (int j = 0; j < 8; j++) {
        *(float2*)&Op[(size_t)r0     * HDIM + j*8 + 2*t] =
            make_float2(tf32r(o[j][0] * inv0), tf32r(o[j][1] * inv0));
        *(float2*)&Op[(size_t)(r0+8) * HDIM + j*8 + 2*t] =
            make_float2(tf32r(o[j][2] * inv1), tf32r(o[j][3] * inv1));
    }
}

// ---------------------------------------------------------------------------
// Launch
// ---------------------------------------------------------------------------
extern "C" void kernel_launch(void* const* d_in, const int* in_sizes, int n_in,
                              void* d_out, int out_size)
{
    const float* data = (const float*)d_in[0];
    const float* gk   = (const float*)d_in[1];
    const float* bk   = (const float*)d_in[2];
    const float* gq   = (const float*)d_in[3];
    const float* bq   = (const float*)d_in[4];
    const float* gv   = (const float*)d_in[5];
    const float* bv   = (const float*)d_in[6];
    const float* Wq   = (const float*)d_in[7];
    const float* bq2  = (const float*)d_in[8];
    const float* Wk   = (const float*)d_in[9];
    const float* bk2  = (const float*)d_in[10];
    const float* Wv   = (const float*)d_in[11];
    const float* bv2  = (const float*)d_in[12];
    const float* Wo   = (const float*)d_in[13];
    const float* bo   = (const float*)d_in[14];
    float* out = (float*)d_out;

    float *xq, *xk, *xv, *Q, *K, *V, *Kt, *Vt, *O, *rWq, *rWk, *rWv, *rWo;
    cudaGetSymbolAddress((void**)&xq, g_xq);
    cudaGetSymbolAddress((void**)&xk, g_xk);
    cudaGetSymbolAddress((void**)&xv, g_xv);
    cudaGetSymbolAddress((void**)&Q,  g_Q);
    cudaGetSymbolAddress((void**)&K,  g_K);
    cudaGetSymbolAddress((void**)&V,  g_V);
    cudaGetSymbolAddress((void**)&Kt, g_Kt);
    cudaGetSymbolAddress((void**)&Vt, g_Vt);
    cudaGetSymbolAddress((void**)&O,  g_O);
    cudaGetSymbolAddress((void**)&rWq, g_Wq);
    cudaGetSymbolAddress((void**)&rWk, g_Wk);
    cudaGetSymbolAddress((void**)&rWv, g_Wv);
    cudaGetSymbolAddress((void**)&rWo, g_Wo);

    static int attr_done = 0;
    if (!attr_done) {
        cudaFuncSetAttribute(attn_fused, cudaFuncAttributeMaxDynamicSharedMemorySize, ATTN_SMEM);
        attr_done = 1;
    }

    dim3 rwgrid(DD * DD / 4 / 256, 4);          // (1024, 4)
    roundw_all<<<rwgrid, 256>>>(Wq, Wk, Wv, Wo, rWq, rWk, rWv, rWo);

    ln3_kernel<<<TOK, 256>>>(data, gk, bk, gq, bq, gv, bv, xq, xk, xv);

    dim3 qkvgrid(DD / 128, TOK / 128, 3);       // (8, 32, 3)
    gemm_qkv<<<qkvgrid, 256>>>(xq, xk, xv, rWq, rWk, rWv, bq2, bk2, bv2, Q, K, V);

    dim3 tgrid(SS / 32, HDIM / 32, 2 * BB * HH);
    dim3 tblk(32, 8);
    transpose_both<<<tgrid, tblk>>>(K, Kt, V, Vt);

    dim3 agrid(SS / 128, BB * HH);              // (16, 32)
    attn_fused<<<agrid, 256, ATTN_SMEM>>>(Q, K, Kt, Vt, O);

    dim3 ogrid(DD / 128, TOK / 128);            // (8, 32)
    gemm_out<<<ogrid, 256>>>(O, rWo, bo, out);
}